// round 1
// baseline (speedup 1.0000x reference)
#include <cuda_runtime.h>

#define T_LEN   12
#define N_HEADS 8
#define N_NODES 16384
#define H_DIM   64
#define G_DIM   256      // 4 * H_DIM gates
#define NB      64       // nodes per CTA
#define INPAD   68       // padded row stride for transposed activation tiles

#define SM_W    (H_DIM * G_DIM)     // 16384 floats per weight matrix (transposed [d][g])
#define SM_ACT  (H_DIM * INPAD)     // 4352 floats per activation tile [d][n]
#define SMEM_FLOATS (2 * SM_W + 2 * SM_ACT)
#define SMEM_BYTES  (SMEM_FLOATS * 4)

// Scratch: hs per layer, layout [head][t][node][hd]  (head-major channel order for conv)
__device__ float g_hs0[(size_t)N_HEADS * T_LEN * N_NODES * H_DIM];
__device__ float g_hs1[(size_t)N_HEADS * T_LEN * N_NODES * H_DIM];

__device__ __forceinline__ float sigf(float v) {
    return __fdividef(1.0f, 1.0f + __expf(-v));
}
__device__ __forceinline__ float tanh_fast(float v) {
    return __fdividef(2.0f, 1.0f + __expf(-2.0f * v)) - 1.0f;
}

__global__ __launch_bounds__(256, 1)
void lstm_fused_kernel(const float* __restrict__ x,
                       const float* __restrict__ W_ih,
                       const float* __restrict__ W_hh,
                       const float* __restrict__ b_ih,
                       const float* __restrict__ b_hh,
                       const float* __restrict__ h0,
                       const float* __restrict__ c0)
{
    extern __shared__ float sm[];
    float* sWih = sm;                       // [64][256]  Wt[d][g]
    float* sWhh = sm + SM_W;                // [64][256]
    float* sIn  = sm + 2 * SM_W;            // [64][INPAD]  in_T[d][n]
    float* sH   = sm + 2 * SM_W + SM_ACT;   // [64][INPAD]  h_T[d][n]

    const int tid   = threadIdx.x;
    const int a     = blockIdx.y;           // head
    const int node0 = blockIdx.x * NB;      // node tile base
    const int hd0   = (tid & 15) * 4;       // 4 hidden dims owned by this thread
    const int n0    = (tid >> 4) * 4;       // 4 nodes owned by this thread

    float c_state[4][4];   // [node][hd]
    float bias_r[4][4];    // [gate][hd]

    for (int l = 0; l < 2; ++l) {
        // ---- load weights, transposed into SMEM ----
        const float* Wih_g = W_ih + (size_t)(l * N_HEADS + a) * (G_DIM * H_DIM);
        const float* Whh_g = W_hh + (size_t)(l * N_HEADS + a) * (G_DIM * H_DIM);
        #pragma unroll 1
        for (int i = 0; i < 64; ++i) {
            int idx = i * 256 + tid;        // 16384 elements, coalesced read
            int g = idx >> 6, d = idx & 63;
            sWih[d * 256 + g] = Wih_g[idx];
            sWhh[d * 256 + g] = Whh_g[idx];
        }
        // ---- per-thread biases ----
        {
            const float* bi = b_ih + (size_t)(l * N_HEADS + a) * G_DIM;
            const float* bh = b_hh + (size_t)(l * N_HEADS + a) * G_DIM;
            #pragma unroll
            for (int g = 0; g < 4; ++g)
                #pragma unroll
                for (int j = 0; j < 4; ++j) {
                    int gg = g * 64 + hd0 + j;
                    bias_r[g][j] = bi[gg] + bh[gg];
                }
        }
        // ---- initial states for this layer ----
        {
            size_t st_base = ((size_t)(a * 2 + l) * N_NODES + node0) * H_DIM;
            #pragma unroll
            for (int i = 0; i < 4; ++i) {
                size_t off = st_base + (size_t)(n0 + i) * H_DIM + hd0;
                float4 cv = *(const float4*)(c0 + off);
                float4 hv = *(const float4*)(h0 + off);
                c_state[i][0] = cv.x; c_state[i][1] = cv.y;
                c_state[i][2] = cv.z; c_state[i][3] = cv.w;
                sH[(hd0 + 0) * INPAD + n0 + i] = hv.x;
                sH[(hd0 + 1) * INPAD + n0 + i] = hv.y;
                sH[(hd0 + 2) * INPAD + n0 + i] = hv.z;
                sH[(hd0 + 3) * INPAD + n0 + i] = hv.w;
            }
        }

        const float* in_base = (l == 0) ? x
                             : (g_hs0 + (size_t)a * T_LEN * N_NODES * H_DIM);
        float* out_base = ((l == 0) ? g_hs0 : g_hs1)
                        + (size_t)a * T_LEN * N_NODES * H_DIM;

        for (int t = 0; t < T_LEN; ++t) {
            // ---- stage input tile transposed into SMEM ----
            const float* src = in_base + ((size_t)t * N_NODES + node0) * H_DIM;
            #pragma unroll
            for (int k = 0; k < 4; ++k) {
                int idx4 = k * 256 + tid;     // 1024 float4 tiles
                int n  = idx4 >> 4;
                int d4 = (idx4 & 15) * 4;
                float4 v = *(const float4*)(src + n * H_DIM + d4);
                sIn[(d4 + 0) * INPAD + n] = v.x;
                sIn[(d4 + 1) * INPAD + n] = v.y;
                sIn[(d4 + 2) * INPAD + n] = v.z;
                sIn[(d4 + 3) * INPAD + n] = v.w;
            }
            __syncthreads();   // sIn ready; sH from prev step / init visible

            // ---- gates = in @ Wih^T + h @ Whh^T + bias ----
            float acc[4][4][4];   // [node][gate][hd]
            #pragma unroll
            for (int i = 0; i < 4; ++i)
                #pragma unroll
                for (int g = 0; g < 4; ++g)
                    #pragma unroll
                    for (int j = 0; j < 4; ++j)
                        acc[i][g][j] = bias_r[g][j];

            #pragma unroll 8
            for (int d = 0; d < 64; ++d) {
                float4 in4 = *(const float4*)(sIn + d * INPAD + n0);
                float4 h4  = *(const float4*)(sH  + d * INPAD + n0);
                float inn[4] = {in4.x, in4.y, in4.z, in4.w};
                float hhv[4] = {h4.x,  h4.y,  h4.z,  h4.w};
                const float* wrow_i = sWih + d * 256 + hd0;
                const float* wrow_h = sWhh + d * 256 + hd0;
                #pragma unroll
                for (int g = 0; g < 4; ++g) {
                    float4 wi4 = *(const float4*)(wrow_i + g * 64);
                    float4 wh4 = *(const float4*)(wrow_h + g * 64);
                    float wi[4] = {wi4.x, wi4.y, wi4.z, wi4.w};
                    float wh[4] = {wh4.x, wh4.y, wh4.z, wh4.w};
                    #pragma unroll
                    for (int i = 0; i < 4; ++i)
                        #pragma unroll
                        for (int j = 0; j < 4; ++j)
                            acc[i][g][j] += inn[i] * wi[j] + hhv[i] * wh[j];
                }
            }
            __syncthreads();   // all GEMM reads of sIn/sH done

            // ---- elementwise LSTM cell + write h ----
            #pragma unroll
            for (int i = 0; i < 4; ++i) {
                float hv[4];
                #pragma unroll
                for (int j = 0; j < 4; ++j) {
                    float ig = acc[i][0][j];
                    float fg = acc[i][1][j];
                    float gg = acc[i][2][j];
                    float og = acc[i][3][j];
                    float cc = sigf(fg) * c_state[i][j] + sigf(ig) * tanh_fast(gg);
                    c_state[i][j] = cc;
                    hv[j] = sigf(og) * tanh_fast(cc);
                }
                sH[(hd0 + 0) * INPAD + n0 + i] = hv[0];
                sH[(hd0 + 1) * INPAD + n0 + i] = hv[1];
                sH[(hd0 + 2) * INPAD + n0 + i] = hv[2];
                sH[(hd0 + 3) * INPAD + n0 + i] = hv[3];
                float4 o4 = make_float4(hv[0], hv[1], hv[2], hv[3]);
                *(float4*)(out_base + ((size_t)t * N_NODES + node0 + n0 + i) * H_DIM + hd0) = o4;
            }
            // no trailing sync needed: next iteration's sIn writes touch a
            // different buffer, and its post-load sync orders these sH writes.
        }
        __syncthreads();   // safety: before next layer overwrites weights
    }
}

// out[o][n][hd] = sum_c hs1[c][n][hd] * conv_w[o][c] + conv_b[o],  c = a*T + t
__global__ __launch_bounds__(256)
void conv_kernel(const float* __restrict__ conv_w,
                 const float* __restrict__ conv_b,
                 float* __restrict__ out)
{
    __shared__ float sw[T_LEN * N_HEADS * T_LEN];   // [12][96]
    __shared__ float sb[T_LEN];
    for (int i = threadIdx.x; i < T_LEN * N_HEADS * T_LEN; i += 256)
        sw[i] = conv_w[i];
    if (threadIdx.x < T_LEN) sb[threadIdx.x] = conv_b[threadIdx.x];
    __syncthreads();

    const size_t stride = (size_t)N_NODES * H_DIM;   // per-channel stride
    size_t nh4 = ((size_t)blockIdx.x * 256 + threadIdx.x) * 4;  // 4 elems / thread

    float acc[T_LEN][4];
    #pragma unroll
    for (int o = 0; o < T_LEN; ++o) {
        float b = sb[o];
        acc[o][0] = b; acc[o][1] = b; acc[o][2] = b; acc[o][3] = b;
    }
    #pragma unroll 4
    for (int c = 0; c < N_HEADS * T_LEN; ++c) {
        float4 v = *(const float4*)(g_hs1 + (size_t)c * stride + nh4);
        #pragma unroll
        for (int o = 0; o < T_LEN; ++o) {
            float w = sw[o * (N_HEADS * T_LEN) + c];
            acc[o][0] += v.x * w;
            acc[o][1] += v.y * w;
            acc[o][2] += v.z * w;
            acc[o][3] += v.w * w;
        }
    }
    #pragma unroll
    for (int o = 0; o < T_LEN; ++o) {
        float4 r = make_float4(acc[o][0], acc[o][1], acc[o][2], acc[o][3]);
        *(float4*)(out + (size_t)o * stride + nh4) = r;
    }
}

extern "C" void kernel_launch(void* const* d_in, const int* in_sizes, int n_in,
                              void* d_out, int out_size)
{
    const float* x      = (const float*)d_in[0];
    const float* W_ih   = (const float*)d_in[1];
    const float* W_hh   = (const float*)d_in[2];
    const float* b_ih   = (const float*)d_in[3];
    const float* b_hh   = (const float*)d_in[4];
    const float* h0     = (const float*)d_in[5];
    const float* c0     = (const float*)d_in[6];
    const float* conv_w = (const float*)d_in[7];
    const float* conv_b = (const float*)d_in[8];
    float* out = (float*)d_out;

    cudaFuncSetAttribute(lstm_fused_kernel,
                         cudaFuncAttributeMaxDynamicSharedMemorySize, SMEM_BYTES);

    dim3 grid(N_NODES / NB, N_HEADS);    // 256 x 8 = 2048 CTAs
    lstm_fused_kernel<<<grid, 256, SMEM_BYTES>>>(x, W_ih, W_hh, b_ih, b_hh, h0, c0);

    // N*H / 4 elems-per-thread / 256 threads = 1024 blocks
    conv_kernel<<<(N_NODES * H_DIM) / (4 * 256), 256>>>(conv_w, conv_b, out);
}

// round 2
// speedup vs baseline: 1.1366x; 1.1366x over previous
#include <cuda_runtime.h>

#define T_LEN   12
#define N_HEADS 8
#define N_NODES 16384
#define H_DIM   64
#define G_DIM   256      // 4 * H_DIM gates
#define NB      64       // nodes per CTA
#define ASTR    132      // activation row stride (floats), duplicated pairs: [d][2n+r]

#define SM_W    (H_DIM * G_DIM)     // 16384 floats per transposed weight matrix [d][g]
#define SM_ACT  (H_DIM * ASTR)      // 8448 floats per duplicated activation tile
#define SMEM_FLOATS (2 * SM_W + 2 * SM_ACT)
#define SMEM_BYTES  (SMEM_FLOATS * 4)

// Scratch: hs per layer, layout [head][t][node][hd]  (head-major channel order for conv)
__device__ float g_hs0[(size_t)N_HEADS * T_LEN * N_NODES * H_DIM];
__device__ float g_hs1[(size_t)N_HEADS * T_LEN * N_NODES * H_DIM];

typedef unsigned long long u64;

__device__ __forceinline__ u64 fma2(u64 a, u64 b, u64 c) {
    u64 d;
    asm("fma.rn.f32x2 %0, %1, %2, %3;" : "=l"(d) : "l"(a), "l"(b), "l"(c));
    return d;
}
__device__ __forceinline__ u64 pack2(float a, float b) {
    u64 r;
    asm("mov.b64 %0, {%1, %2};" : "=l"(r) : "f"(a), "f"(b));
    return r;
}
__device__ __forceinline__ void unpack2(u64 v, float& lo, float& hi) {
    asm("mov.b64 {%0, %1}, %2;" : "=f"(lo), "=f"(hi) : "l"(v));
}

__device__ __forceinline__ float sigf(float v) {
    return __fdividef(1.0f, 1.0f + __expf(-v));
}
__device__ __forceinline__ float tanh_fast(float v) {
    return __fdividef(2.0f, 1.0f + __expf(-2.0f * v)) - 1.0f;
}

__global__ __launch_bounds__(256, 1)
void lstm_fused_kernel(const float* __restrict__ x,
                       const float* __restrict__ W_ih,
                       const float* __restrict__ W_hh,
                       const float* __restrict__ b_ih,
                       const float* __restrict__ b_hh,
                       const float* __restrict__ h0,
                       const float* __restrict__ c0)
{
    extern __shared__ float sm[];
    float* sWih = sm;                       // [64][256]  Wt[d][g]
    float* sWhh = sm + SM_W;                // [64][256]
    float* sIn  = sm + 2 * SM_W;            // [64][ASTR]  in dup: [d][2n+r]
    float* sH   = sm + 2 * SM_W + SM_ACT;   // [64][ASTR]  h  dup: [d][2n+r]

    const int tid   = threadIdx.x;
    const int a     = blockIdx.y;           // head
    const int node0 = blockIdx.x * NB;      // node tile base
    const int hd0   = (tid & 15) * 4;       // 4 hidden dims owned by this thread
    const int n0    = (tid >> 4) * 4;       // 4 nodes owned by this thread

    float c_state[4][4];   // [node][hd]
    u64   bias2[4][2];     // [gate][hd-pair], packed (b[2p], b[2p+1])

    for (int l = 0; l < 2; ++l) {
        // ---- load weights, transposed into SMEM ----
        const float* Wih_g = W_ih + (size_t)(l * N_HEADS + a) * (G_DIM * H_DIM);
        const float* Whh_g = W_hh + (size_t)(l * N_HEADS + a) * (G_DIM * H_DIM);
        #pragma unroll 1
        for (int i = 0; i < 64; ++i) {
            int idx = i * 256 + tid;        // 16384 elements, coalesced read
            int g = idx >> 6, d = idx & 63;
            sWih[d * 256 + g] = Wih_g[idx];
            sWhh[d * 256 + g] = Whh_g[idx];
        }
        // ---- per-thread packed biases ----
        {
            const float* bi = b_ih + (size_t)(l * N_HEADS + a) * G_DIM;
            const float* bh = b_hh + (size_t)(l * N_HEADS + a) * G_DIM;
            #pragma unroll
            for (int g = 0; g < 4; ++g)
                #pragma unroll
                for (int p = 0; p < 2; ++p) {
                    int g0 = g * 64 + hd0 + 2 * p;
                    bias2[g][p] = pack2(bi[g0] + bh[g0], bi[g0 + 1] + bh[g0 + 1]);
                }
        }
        // ---- initial states for this layer ----
        {
            size_t st_base = ((size_t)(a * 2 + l) * N_NODES + node0) * H_DIM;
            #pragma unroll
            for (int i = 0; i < 4; ++i) {
                size_t off = st_base + (size_t)(n0 + i) * H_DIM + hd0;
                float4 cv = *(const float4*)(c0 + off);
                float4 hv = *(const float4*)(h0 + off);
                c_state[i][0] = cv.x; c_state[i][1] = cv.y;
                c_state[i][2] = cv.z; c_state[i][3] = cv.w;
                int col = 2 * (n0 + i);
                *(u64*)(sH + (hd0 + 0) * ASTR + col) = pack2(hv.x, hv.x);
                *(u64*)(sH + (hd0 + 1) * ASTR + col) = pack2(hv.y, hv.y);
                *(u64*)(sH + (hd0 + 2) * ASTR + col) = pack2(hv.z, hv.z);
                *(u64*)(sH + (hd0 + 3) * ASTR + col) = pack2(hv.w, hv.w);
            }
        }

        const float* in_base = (l == 0) ? x
                             : (g_hs0 + (size_t)a * T_LEN * N_NODES * H_DIM);
        float* out_base = ((l == 0) ? g_hs0 : g_hs1)
                        + (size_t)a * T_LEN * N_NODES * H_DIM;

        for (int t = 0; t < T_LEN; ++t) {
            // ---- stage input tile transposed + duplicated into SMEM ----
            const float* src = in_base + ((size_t)t * N_NODES + node0) * H_DIM;
            #pragma unroll
            for (int k = 0; k < 4; ++k) {
                int idx4 = k * 256 + tid;     // 1024 float4 tiles
                int n  = idx4 >> 4;
                int d4 = (idx4 & 15) * 4;
                float4 v = *(const float4*)(src + n * H_DIM + d4);
                int col = 2 * n;
                *(u64*)(sIn + (d4 + 0) * ASTR + col) = pack2(v.x, v.x);
                *(u64*)(sIn + (d4 + 1) * ASTR + col) = pack2(v.y, v.y);
                *(u64*)(sIn + (d4 + 2) * ASTR + col) = pack2(v.z, v.z);
                *(u64*)(sIn + (d4 + 3) * ASTR + col) = pack2(v.w, v.w);
            }
            __syncthreads();   // sIn ready; sH writes (init / prev cell) visible

            // ---- gates = in @ Wih^T + h @ Whh^T + bias  (packed f32x2) ----
            u64 acc2[4][4][2];   // [node][gate][hd-pair]
            #pragma unroll
            for (int i = 0; i < 4; ++i)
                #pragma unroll
                for (int g = 0; g < 4; ++g) {
                    acc2[i][g][0] = bias2[g][0];
                    acc2[i][g][1] = bias2[g][1];
                }

            #pragma unroll 8
            for (int d = 0; d < 64; ++d) {
                const float* sInD = sIn + d * ASTR + 2 * n0;
                const float* sHD  = sH  + d * ASTR + 2 * n0;
                ulonglong2 inA = *(const ulonglong2*)(sInD);      // nodes n0, n0+1 (dup)
                ulonglong2 inB = *(const ulonglong2*)(sInD + 4);  // nodes n0+2, n0+3
                ulonglong2 hA  = *(const ulonglong2*)(sHD);
                ulonglong2 hB  = *(const ulonglong2*)(sHD + 4);
                u64 inn2[4] = {inA.x, inA.y, inB.x, inB.y};
                u64 hh2[4]  = {hA.x,  hA.y,  hB.x,  hB.y};
                const float* wrow_i = sWih + d * 256 + hd0;
                const float* wrow_h = sWhh + d * 256 + hd0;
                #pragma unroll
                for (int g = 0; g < 4; ++g) {
                    ulonglong2 wi = *(const ulonglong2*)(wrow_i + g * 64);
                    ulonglong2 wh = *(const ulonglong2*)(wrow_h + g * 64);
                    #pragma unroll
                    for (int i = 0; i < 4; ++i) {
                        acc2[i][g][0] = fma2(inn2[i], wi.x, fma2(hh2[i], wh.x, acc2[i][g][0]));
                        acc2[i][g][1] = fma2(inn2[i], wi.y, fma2(hh2[i], wh.y, acc2[i][g][1]));
                    }
                }
            }
            __syncthreads();   // all GEMM reads of sIn/sH done

            // ---- elementwise LSTM cell + write h (dup to SMEM, plain to GMEM) ----
            #pragma unroll
            for (int i = 0; i < 4; ++i) {
                float gate[4][4];   // [g][j]
                #pragma unroll
                for (int g = 0; g < 4; ++g) {
                    unpack2(acc2[i][g][0], gate[g][0], gate[g][1]);
                    unpack2(acc2[i][g][1], gate[g][2], gate[g][3]);
                }
                float hv[4];
                #pragma unroll
                for (int j = 0; j < 4; ++j) {
                    float cc = sigf(gate[1][j]) * c_state[i][j]
                             + sigf(gate[0][j]) * tanh_fast(gate[2][j]);
                    c_state[i][j] = cc;
                    hv[j] = sigf(gate[3][j]) * tanh_fast(cc);
                }
                int col = 2 * (n0 + i);
                *(u64*)(sH + (hd0 + 0) * ASTR + col) = pack2(hv[0], hv[0]);
                *(u64*)(sH + (hd0 + 1) * ASTR + col) = pack2(hv[1], hv[1]);
                *(u64*)(sH + (hd0 + 2) * ASTR + col) = pack2(hv[2], hv[2]);
                *(u64*)(sH + (hd0 + 3) * ASTR + col) = pack2(hv[3], hv[3]);
                float4 o4 = make_float4(hv[0], hv[1], hv[2], hv[3]);
                *(float4*)(out_base + ((size_t)t * N_NODES + node0 + n0 + i) * H_DIM + hd0) = o4;
            }
            // next iteration's post-staging __syncthreads orders these sH writes
        }
        __syncthreads();   // before next layer overwrites weights
    }
}

// out[o][n][hd] = sum_c hs1[c][n][hd] * conv_w[o][c] + conv_b[o],  c = a*T + t
__global__ __launch_bounds__(256)
void conv_kernel(const float* __restrict__ conv_w,
                 const float* __restrict__ conv_b,
                 float* __restrict__ out)
{
    __shared__ float sw[T_LEN * N_HEADS * T_LEN];   // [12][96]
    __shared__ float sb[T_LEN];
    for (int i = threadIdx.x; i < T_LEN * N_HEADS * T_LEN; i += 256)
        sw[i] = conv_w[i];
    if (threadIdx.x < T_LEN) sb[threadIdx.x] = conv_b[threadIdx.x];
    __syncthreads();

    const size_t stride = (size_t)N_NODES * H_DIM;   // per-channel stride
    size_t nh4 = ((size_t)blockIdx.x * 256 + threadIdx.x) * 4;  // 4 elems / thread

    float acc[T_LEN][4];
    #pragma unroll
    for (int o = 0; o < T_LEN; ++o) {
        float b = sb[o];
        acc[o][0] = b; acc[o][1] = b; acc[o][2] = b; acc[o][3] = b;
    }
    #pragma unroll 4
    for (int c = 0; c < N_HEADS * T_LEN; ++c) {
        float4 v = *(const float4*)(g_hs1 + (size_t)c * stride + nh4);
        #pragma unroll
        for (int o = 0; o < T_LEN; ++o) {
            float w = sw[o * (N_HEADS * T_LEN) + c];
            acc[o][0] += v.x * w;
            acc[o][1] += v.y * w;
            acc[o][2] += v.z * w;
            acc[o][3] += v.w * w;
        }
    }
    #pragma unroll
    for (int o = 0; o < T_LEN; ++o) {
        float4 r = make_float4(acc[o][0], acc[o][1], acc[o][2], acc[o][3]);
        *(float4*)(out + (size_t)o * stride + nh4) = r;
    }
}

extern "C" void kernel_launch(void* const* d_in, const int* in_sizes, int n_in,
                              void* d_out, int out_size)
{
    const float* x      = (const float*)d_in[0];
    const float* W_ih   = (const float*)d_in[1];
    const float* W_hh   = (const float*)d_in[2];
    const float* b_ih   = (const float*)d_in[3];
    const float* b_hh   = (const float*)d_in[4];
    const float* h0     = (const float*)d_in[5];
    const float* c0     = (const float*)d_in[6];
    const float* conv_w = (const float*)d_in[7];
    const float* conv_b = (const float*)d_in[8];
    float* out = (float*)d_out;

    cudaFuncSetAttribute(lstm_fused_kernel,
                         cudaFuncAttributeMaxDynamicSharedMemorySize, SMEM_BYTES);

    dim3 grid(N_NODES / NB, N_HEADS);    // 256 x 8 = 2048 CTAs
    lstm_fused_kernel<<<grid, 256, SMEM_BYTES>>>(x, W_ih, W_hh, b_ih, b_hh, h0, c0);

    conv_kernel<<<(N_NODES * H_DIM) / (4 * 256), 256>>>(conv_w, conv_b, out);
}

// round 4
// speedup vs baseline: 2.9346x; 2.5820x over previous
#include <cuda_runtime.h>
#include <cuda_bf16.h>
#include <cstdint>

#define T_LEN   12
#define N_HEADS 8
#define N_NODES 16384
#define H_DIM   64
#define G_DIM   256
#define NB      128          // nodes per CTA (= GEMM M)
#define THREADS 256

// ---- shared memory layout (bytes) ----
#define SA_HI   0            // A tile hi: [128 rows][128 k] bf16 swizzled   (32768)
#define SA_LO   32768        // A tile lo                                    (32768)
#define SB_HI   65536        // B tile hi: [256 rows][128 k] bf16            (65536)
#define SB_LO   131072       // B tile lo                                    (65536)
#define SXS     196608       // x staging fp32 [128][64]                     (32768)
#define SBIAS   229376       // bias fp32 [256]                              (1024)
#define SMEM_TOTAL 230400

// Scratch: hs per layer, [head][t][node][hd]
__device__ float g_hs0[(size_t)N_HEADS * T_LEN * N_NODES * H_DIM];
__device__ float g_hs1[(size_t)N_HEADS * T_LEN * N_NODES * H_DIM];

// swizzled byte offset in [R rows][128 k] bf16 tile; R8 = R/8, k = element idx
__device__ __forceinline__ uint32_t swzoff(int R8, int row, int k) {
    uint32_t off = (uint32_t)((((row >> 3) + (k >> 6) * R8) << 10)
                 + ((row & 7) << 7) + ((k & 63) << 1));
    return off ^ ((off >> 3) & 0x70);
}

__device__ __forceinline__ uint32_t smem_u32(const void* p) {
    uint32_t a;
    asm("{ .reg .u64 t; cvta.to.shared.u64 t, %1; cvt.u32.u64 %0, t; }" : "=r"(a) : "l"(p));
    return a;
}

__device__ __forceinline__ void ldsm4(uint32_t* r, uint32_t addr) {
    asm volatile("ldmatrix.sync.aligned.m8n8.x4.shared.b16 {%0,%1,%2,%3}, [%4];"
        : "=r"(r[0]), "=r"(r[1]), "=r"(r[2]), "=r"(r[3]) : "r"(addr));
}

__device__ __forceinline__ void mma_bf16(float* c, const uint32_t* a,
                                         uint32_t b0, uint32_t b1) {
    asm volatile("mma.sync.aligned.m16n8k16.row.col.f32.bf16.bf16.f32 "
        "{%0,%1,%2,%3}, {%4,%5,%6,%7}, {%8,%9}, {%0,%1,%2,%3};"
        : "+f"(c[0]), "+f"(c[1]), "+f"(c[2]), "+f"(c[3])
        : "r"(a[0]), "r"(a[1]), "r"(a[2]), "r"(a[3]), "r"(b0), "r"(b1));
}

#define CP_ASYNC16(dst_u32, src) \
    asm volatile("cp.async.cg.shared.global [%0], [%1], 16;" :: "r"(dst_u32), "l"(src) : "memory")
#define CP_COMMIT() asm volatile("cp.async.commit_group;" ::: "memory")
#define CP_WAIT0()  asm volatile("cp.async.wait_group 0;" ::: "memory")

__device__ __forceinline__ float sigf(float v) {
    return __fdividef(1.0f, 1.0f + __expf(-v));
}
__device__ __forceinline__ float tanh_fast(float v) {
    return __fdividef(2.0f, 1.0f + __expf(-2.0f * v)) - 1.0f;
}

// split 8 fp32 -> hi/lo bf16, store 16B each into swizzled tiles
__device__ __forceinline__ void split8_store(const float* v, char* smem,
                                             int tileHi, int tileLo, uint32_t off) {
    uint32_t hw[4], lw[4];
    #pragma unroll
    for (int qq = 0; qq < 4; ++qq) {
        float a = v[2 * qq], b = v[2 * qq + 1];
        __nv_bfloat162 hb = __floats2bfloat162_rn(a, b);
        float ar = a - __bfloat162float(hb.x);
        float br = b - __bfloat162float(hb.y);
        __nv_bfloat162 lb = __floats2bfloat162_rn(ar, br);
        hw[qq] = *(uint32_t*)&hb;
        lw[qq] = *(uint32_t*)&lb;
    }
    *(uint4*)(smem + tileHi + off) = make_uint4(hw[0], hw[1], hw[2], hw[3]);
    *(uint4*)(smem + tileLo + off) = make_uint4(lw[0], lw[1], lw[2], lw[3]);
}

__global__ __launch_bounds__(THREADS, 1)
void lstm_mma_kernel(const float* __restrict__ x,
                     const float* __restrict__ W_ih,
                     const float* __restrict__ W_hh,
                     const float* __restrict__ b_ih,
                     const float* __restrict__ b_hh,
                     const float* __restrict__ h0,
                     const float* __restrict__ c0)
{
    extern __shared__ char smem[];
    const uint32_t sbase = smem_u32(smem);
    float* xstage = (float*)(smem + SXS);
    float* sbias  = (float*)(smem + SBIAS);

    const int tid  = threadIdx.x;
    const int warp = tid >> 5;
    const int lane = tid & 31;
    const int wm = warp & 1;            // M-warp (2)
    const int wn = warp >> 1;           // N-warp (4)
    const int mrow0 = wm * 64;
    const int nbase = wn * 64;          // permuted-B row base
    const int gid = lane >> 2;
    const int q   = lane & 3;
    const int jg  = wn * 16 + q * 4;    // this thread's hd base (4 contiguous)

    // ldmatrix per-lane row/k components
    const int a_row_lane = ((lane >> 3) & 1) * 8 + (lane & 7);
    const int a_kadd     = (lane >> 4) * 8;
    const int b_row_lane = (lane >> 4) * 8 + (lane & 7);
    const int b_kadd     = ((lane >> 3) & 1) * 8;

    const int head  = blockIdx.y;
    const int node0 = blockIdx.x * NB;

    float c_reg[4][2][4];   // [mtile][rowhalf][joff]

    for (int l = 0; l < 2; ++l) {
        // ======== layer prologue ========
        const float* Wih_g = W_ih + (size_t)(l * N_HEADS + head) * (G_DIM * H_DIM);
        const float* Whh_g = W_hh + (size_t)(l * N_HEADS + head) * (G_DIM * H_DIM);

        // B tile with gate-interleave row permutation:
        // row = (wn<<6)|(t<<3)|(q<<1)|b ; g = ((t&1)<<1)|b ; j = (wn<<4)|(q<<2)|(t>>1)
        #pragma unroll 1
        for (int i = 0; i < 16; ++i) {
            int gidx = tid + i * 256;              // 4096 (row,k8) groups
            int row_out = gidx >> 4;
            int k8 = (gidx & 15) * 8;
            int tt = (row_out >> 3) & 7;
            int qq = (row_out >> 1) & 3;
            int bb = row_out & 1;
            int wnn = row_out >> 6;
            int g  = ((tt & 1) << 1) | bb;
            int jj = (wnn << 4) | (qq << 2) | (tt >> 1);
            const float* src = (k8 < 64) ? (Wih_g + (g * 64 + jj) * 64 + k8)
                                         : (Whh_g + (g * 64 + jj) * 64 + (k8 - 64));
            float v[8];
            float4 v0 = *(const float4*)(src);
            float4 v1 = *(const float4*)(src + 4);
            v[0]=v0.x; v[1]=v0.y; v[2]=v0.z; v[3]=v0.w;
            v[4]=v1.x; v[5]=v1.y; v[6]=v1.z; v[7]=v1.w;
            split8_store(v, smem, SB_HI, SB_LO, swzoff(32, row_out, k8));
        }
        // bias (natural order g*64+j)
        {
            const float* bi = b_ih + (size_t)(l * N_HEADS + head) * G_DIM;
            const float* bh = b_hh + (size_t)(l * N_HEADS + head) * G_DIM;
            sbias[tid] = bi[tid] + bh[tid];
        }
        // h0 -> A h-region (k 64..127)
        {
            const float* hsrc = h0 + ((size_t)(head * 2 + l) * N_NODES + node0) * H_DIM;
            #pragma unroll
            for (int i = 0; i < 4; ++i) {
                int gidx = tid + i * 256;          // 1024 groups
                int n  = gidx >> 3;
                int k8 = (gidx & 7) * 8;
                float v[8];
                float4 v0 = *(const float4*)(hsrc + n * 64 + k8);
                float4 v1 = *(const float4*)(hsrc + n * 64 + k8 + 4);
                v[0]=v0.x; v[1]=v0.y; v[2]=v0.z; v[3]=v0.w;
                v[4]=v1.x; v[5]=v1.y; v[6]=v1.z; v[7]=v1.w;
                split8_store(v, smem, SA_HI, SA_LO, swzoff(16, n, 64 + k8));
            }
        }
        // c0 -> registers
        {
            const float* cbase = c0 + ((size_t)(head * 2 + l) * N_NODES + node0) * H_DIM;
            #pragma unroll
            for (int mt = 0; mt < 4; ++mt)
                #pragma unroll
                for (int rh = 0; rh < 2; ++rh) {
                    int rowL = mrow0 + mt * 16 + gid + rh * 8;
                    float4 v = *(const float4*)(cbase + (size_t)rowL * 64 + jg);
                    c_reg[mt][rh][0]=v.x; c_reg[mt][rh][1]=v.y;
                    c_reg[mt][rh][2]=v.z; c_reg[mt][rh][3]=v.w;
                }
        }
        const float* in_base = (l == 0) ? x : (g_hs0 + (size_t)head * T_LEN * N_NODES * H_DIM);
        float* out_base = ((l == 0) ? g_hs0 : g_hs1) + (size_t)head * T_LEN * N_NODES * H_DIM;

        // x_0 -> staging -> A x-region (self-mapped)
        {
            const float* src0 = in_base + (size_t)node0 * H_DIM;
            #pragma unroll
            for (int i = 0; i < 4; ++i) {
                int gidx = tid + i * 256;
                int n = gidx >> 3, k8 = (gidx & 7) * 8;
                uint32_t d = sbase + SXS + (uint32_t)(n * 64 + k8) * 4;
                CP_ASYNC16(d,      src0 + n * 64 + k8);
                CP_ASYNC16(d + 16, src0 + n * 64 + k8 + 4);
            }
            CP_COMMIT(); CP_WAIT0();
            #pragma unroll
            for (int i = 0; i < 4; ++i) {
                int gidx = tid + i * 256;
                int n = gidx >> 3, k8 = (gidx & 7) * 8;
                float v[8];
                #pragma unroll
                for (int p = 0; p < 8; ++p) v[p] = xstage[n * 64 + k8 + p];
                split8_store(v, smem, SA_HI, SA_LO, swzoff(16, n, k8));
            }
        }
        __syncthreads();

        // ======== scan ========
        for (int t = 0; t < T_LEN; ++t) {
            // accum, bias-initialized: col(nt,b): g=((nt&1)<<1)|b, j=jg+(nt>>1)
            float acc[4][8][4];
            #pragma unroll
            for (int nt = 0; nt < 8; ++nt) {
                float bv0 = sbias[(((nt & 1) << 1) | 0) * 64 + jg + (nt >> 1)];
                float bv1 = sbias[(((nt & 1) << 1) | 1) * 64 + jg + (nt >> 1)];
                #pragma unroll
                for (int mt = 0; mt < 4; ++mt) {
                    acc[mt][nt][0] = bv0; acc[mt][nt][1] = bv1;
                    acc[mt][nt][2] = bv0; acc[mt][nt][3] = bv1;
                }
            }
            // prefetch x_{t+1}
            if (t + 1 < T_LEN) {
                const float* srcn = in_base + ((size_t)(t + 1) * N_NODES + node0) * H_DIM;
                #pragma unroll
                for (int i = 0; i < 4; ++i) {
                    int gidx = tid + i * 256;
                    int n = gidx >> 3, k8 = (gidx & 7) * 8;
                    uint32_t d = sbase + SXS + (uint32_t)(n * 64 + k8) * 4;
                    CP_ASYNC16(d,      srcn + n * 64 + k8);
                    CP_ASYNC16(d + 16, srcn + n * 64 + k8 + 4);
                }
                CP_COMMIT();
            }

            // MMA: 3 passes fused (hi*hi, hi*lo, lo*hi)
            #pragma unroll 1
            for (int kc = 0; kc < 8; ++kc) {
                int k0 = kc * 16;
                uint32_t ah[4][4], al[4][4];
                #pragma unroll
                for (int mt = 0; mt < 4; ++mt) {
                    uint32_t off = swzoff(16, mrow0 + mt * 16 + a_row_lane, k0 + a_kadd);
                    ldsm4(ah[mt], sbase + SA_HI + off);
                    ldsm4(al[mt], sbase + SA_LO + off);
                }
                #pragma unroll
                for (int nt2 = 0; nt2 < 4; ++nt2) {
                    uint32_t off = swzoff(32, nbase + nt2 * 16 + b_row_lane, k0 + b_kadd);
                    uint32_t bh[4], bl[4];
                    ldsm4(bh, sbase + SB_HI + off);
                    ldsm4(bl, sbase + SB_LO + off);
                    #pragma unroll
                    for (int hf = 0; hf < 2; ++hf) {
                        uint32_t bh0 = bh[hf*2], bh1 = bh[hf*2+1];
                        uint32_t bl0 = bl[hf*2], bl1 = bl[hf*2+1];
                        #pragma unroll
                        for (int mt = 0; mt < 4; ++mt) {
                            float* c = acc[mt][nt2 * 2 + hf];
                            mma_bf16(c, ah[mt], bh0, bh1);
                            mma_bf16(c, ah[mt], bl0, bl1);
                            mma_bf16(c, al[mt], bh0, bh1);
                        }
                    }
                }
            }
            __syncthreads();   // all ldmatrix reads of A done before h overwrite

            // epilogue: cell update; thread owns 8 rows x 4 hd (all 4 gates local)
            #pragma unroll
            for (int mt = 0; mt < 4; ++mt)
                #pragma unroll
                for (int rh = 0; rh < 2; ++rh) {
                    int rowL = mrow0 + mt * 16 + gid + rh * 8;
                    float hv[4];
                    #pragma unroll
                    for (int jo = 0; jo < 4; ++jo) {
                        float iv = acc[mt][2*jo  ][rh*2 + 0];
                        float fv = acc[mt][2*jo  ][rh*2 + 1];
                        float gv = acc[mt][2*jo+1][rh*2 + 0];
                        float ov = acc[mt][2*jo+1][rh*2 + 1];
                        float cc = sigf(fv) * c_reg[mt][rh][jo]
                                 + sigf(iv) * tanh_fast(gv);
                        c_reg[mt][rh][jo] = cc;
                        hv[jo] = sigf(ov) * tanh_fast(cc);
                    }
                    // GMEM h (fp32)
                    *(float4*)(out_base + ((size_t)t * N_NODES + node0 + rowL) * H_DIM + jg)
                        = make_float4(hv[0], hv[1], hv[2], hv[3]);
                    // SMEM A h-region (bf16 hi/lo split)
                    __nv_bfloat162 hb0 = __floats2bfloat162_rn(hv[0], hv[1]);
                    __nv_bfloat162 hb1 = __floats2bfloat162_rn(hv[2], hv[3]);
                    float r0 = hv[0] - __bfloat162float(hb0.x);
                    float r1 = hv[1] - __bfloat162float(hb0.y);
                    float r2 = hv[2] - __bfloat162float(hb1.x);
                    float r3 = hv[3] - __bfloat162float(hb1.y);
                    __nv_bfloat162 lb0 = __floats2bfloat162_rn(r0, r1);
                    __nv_bfloat162 lb1 = __floats2bfloat162_rn(r2, r3);
                    uint32_t off = swzoff(16, rowL, 64 + jg);
                    *(uint2*)(smem + SA_HI + off) = make_uint2(*(uint32_t*)&hb0, *(uint32_t*)&hb1);
                    *(uint2*)(smem + SA_LO + off) = make_uint2(*(uint32_t*)&lb0, *(uint32_t*)&lb1);
                }

            // convert x_{t+1} into A x-region
            if (t + 1 < T_LEN) {
                CP_WAIT0();
                #pragma unroll
                for (int i = 0; i < 4; ++i) {
                    int gidx = tid + i * 256;
                    int n = gidx >> 3, k8 = (gidx & 7) * 8;
                    float v[8];
                    #pragma unroll
                    for (int p = 0; p < 8; ++p) v[p] = xstage[n * 64 + k8 + p];
                    split8_store(v, smem, SA_HI, SA_LO, swzoff(16, n, k8));
                }
            }
            __syncthreads();
        }
        __threadfence();   // g_hs0 STGs visible before layer-1 cp.async reads
        __syncthreads();
    }
}

// out[o][n][hd] = sum_c hs1[c][n][hd] * conv_w[o][c] + conv_b[o]
__global__ __launch_bounds__(256)
void conv_kernel(const float* __restrict__ conv_w,
                 const float* __restrict__ conv_b,
                 float* __restrict__ out)
{
    __shared__ float sw[T_LEN * N_HEADS * T_LEN];
    __shared__ float sb[T_LEN];
    for (int i = threadIdx.x; i < T_LEN * N_HEADS * T_LEN; i += 256)
        sw[i] = conv_w[i];
    if (threadIdx.x < T_LEN) sb[threadIdx.x] = conv_b[threadIdx.x];
    __syncthreads();

    const size_t stride = (size_t)N_NODES * H_DIM;
    size_t nh4 = ((size_t)blockIdx.x * 256 + threadIdx.x) * 4;

    float acc[T_LEN][4];
    #pragma unroll
    for (int o = 0; o < T_LEN; ++o) {
        float b = sb[o];
        acc[o][0] = b; acc[o][1] = b; acc[o][2] = b; acc[o][3] = b;
    }
    #pragma unroll 4
    for (int c = 0; c < N_HEADS * T_LEN; ++c) {
        float4 v = *(const float4*)(g_hs1 + (size_t)c * stride + nh4);
        #pragma unroll
        for (int o = 0; o < T_LEN; ++o) {
            float w = sw[o * (N_HEADS * T_LEN) + c];
            acc[o][0] += v.x * w; acc[o][1] += v.y * w;
            acc[o][2] += v.z * w; acc[o][3] += v.w * w;
        }
    }
    #pragma unroll
    for (int o = 0; o < T_LEN; ++o)
        *(float4*)(out + (size_t)o * stride + nh4) =
            make_float4(acc[o][0], acc[o][1], acc[o][2], acc[o][3]);
}

extern "C" void kernel_launch(void* const* d_in, const int* in_sizes, int n_in,
                              void* d_out, int out_size)
{
    const float* x      = (const float*)d_in[0];
    const float* W_ih   = (const float*)d_in[1];
    const float* W_hh   = (const float*)d_in[2];
    const float* b_ih   = (const float*)d_in[3];
    const float* b_hh   = (const float*)d_in[4];
    const float* h0     = (const float*)d_in[5];
    const float* c0     = (const float*)d_in[6];
    const float* conv_w = (const float*)d_in[7];
    const float* conv_b = (const float*)d_in[8];
    float* out = (float*)d_out;

    cudaFuncSetAttribute(lstm_mma_kernel,
                         cudaFuncAttributeMaxDynamicSharedMemorySize, SMEM_TOTAL);

    dim3 grid(N_NODES / NB, N_HEADS);     // 128 x 8 = 1024 CTAs
    lstm_mma_kernel<<<grid, THREADS, SMEM_TOTAL>>>(x, W_ih, W_hh, b_ih, b_hh, h0, c0);

    conv_kernel<<<(N_NODES * H_DIM) / (4 * 256), 256>>>(conv_w, conv_b, out);
}

// round 5
// speedup vs baseline: 3.8837x; 1.3234x over previous
#include <cuda_runtime.h>
#include <cuda_fp16.h>
#include <cstdint>

#define T_LEN   12
#define N_HEADS 8
#define N_NODES 16384
#define H_DIM   64
#define G_DIM   256
#define NB      128          // nodes per CTA (= GEMM M)
#define THREADS 512

// ---- shared memory layout (bytes) ----
#define SA      0            // A tile: [128 rows][128 k] fp16 swizzled       (32768)
#define SB_HI   32768        // B tile hi: [256 rows][128 k] fp16             (65536)
#define SB_LO   98304        // B tile lo                                     (65536)
#define SBIAS   163840       // bias fp32 [256]                               (1024)
#define SMEM_TOTAL 164864

// Scratch: hs per layer, [head][t][node][hd]
__device__ float g_hs0[(size_t)N_HEADS * T_LEN * N_NODES * H_DIM];
__device__ float g_hs1[(size_t)N_HEADS * T_LEN * N_NODES * H_DIM];

// swizzled byte offset in [R rows][128 k] fp16 tile; R8 = R/8, k = element idx
__device__ __forceinline__ uint32_t swzoff(int R8, int row, int k) {
    uint32_t off = (uint32_t)((((row >> 3) + (k >> 6) * R8) << 10)
                 + ((row & 7) << 7) + ((k & 63) << 1));
    return off ^ ((off >> 3) & 0x70);
}

__device__ __forceinline__ uint32_t smem_u32(const void* p) {
    uint32_t a;
    asm("{ .reg .u64 t; cvta.to.shared.u64 t, %1; cvt.u32.u64 %0, t; }" : "=r"(a) : "l"(p));
    return a;
}

__device__ __forceinline__ void ldsm4(uint32_t* r, uint32_t addr) {
    asm volatile("ldmatrix.sync.aligned.m8n8.x4.shared.b16 {%0,%1,%2,%3}, [%4];"
        : "=r"(r[0]), "=r"(r[1]), "=r"(r[2]), "=r"(r[3]) : "r"(addr));
}

__device__ __forceinline__ void mma_f16(float* c, const uint32_t* a,
                                        uint32_t b0, uint32_t b1) {
    asm volatile("mma.sync.aligned.m16n8k16.row.col.f32.f16.f16.f32 "
        "{%0,%1,%2,%3}, {%4,%5,%6,%7}, {%8,%9}, {%0,%1,%2,%3};"
        : "+f"(c[0]), "+f"(c[1]), "+f"(c[2]), "+f"(c[3])
        : "r"(a[0]), "r"(a[1]), "r"(a[2]), "r"(a[3]), "r"(b0), "r"(b1));
}

__device__ __forceinline__ float sigf(float v) {
    return __fdividef(1.0f, 1.0f + __expf(-v));
}
__device__ __forceinline__ float tanh_fast(float v) {
    return __fdividef(2.0f, 1.0f + __expf(-2.0f * v)) - 1.0f;
}

// 8 fp32 -> 8 fp16, one 16B store into swizzled A tile
__device__ __forceinline__ void cvt8_store_f16(const float* v, char* smem,
                                               int tile, uint32_t off) {
    uint32_t w[4];
    #pragma unroll
    for (int qq = 0; qq < 4; ++qq) {
        __half2 h = __floats2half2_rn(v[2 * qq], v[2 * qq + 1]);
        w[qq] = *(uint32_t*)&h;
    }
    *(uint4*)(smem + tile + off) = make_uint4(w[0], w[1], w[2], w[3]);
}

// split 8 fp32 -> hi/lo fp16, 16B store each (B weights)
__device__ __forceinline__ void split8_store_f16(const float* v, char* smem,
                                                 int tileHi, int tileLo, uint32_t off) {
    uint32_t hw[4], lw[4];
    #pragma unroll
    for (int qq = 0; qq < 4; ++qq) {
        float a = v[2 * qq], b = v[2 * qq + 1];
        __half2 hb = __floats2half2_rn(a, b);
        float ar = a - __half2float(__low2half(hb));
        float br = b - __half2float(__high2half(hb));
        __half2 lb = __floats2half2_rn(ar, br);
        hw[qq] = *(uint32_t*)&hb;
        lw[qq] = *(uint32_t*)&lb;
    }
    *(uint4*)(smem + tileHi + off) = make_uint4(hw[0], hw[1], hw[2], hw[3]);
    *(uint4*)(smem + tileLo + off) = make_uint4(lw[0], lw[1], lw[2], lw[3]);
}

__global__ __launch_bounds__(THREADS, 1)
void lstm_mma_kernel(const float* __restrict__ x,
                     const float* __restrict__ W_ih,
                     const float* __restrict__ W_hh,
                     const float* __restrict__ b_ih,
                     const float* __restrict__ b_hh,
                     const float* __restrict__ h0,
                     const float* __restrict__ c0)
{
    extern __shared__ char smem[];
    const uint32_t sbase = smem_u32(smem);
    float* sbias = (float*)(smem + SBIAS);

    const int tid  = threadIdx.x;
    const int warp = tid >> 5;
    const int lane = tid & 31;
    const int wm = warp & 3;            // M-warp (4)
    const int wn = warp >> 2;           // N-warp (4)
    const int mrow0 = wm * 32;
    const int nbase = wn * 64;          // permuted-B row base
    const int gid = lane >> 2;
    const int q   = lane & 3;
    const int jg  = wn * 16 + q * 4;    // this thread's hd base (4 contiguous)

    const int a_row_lane = ((lane >> 3) & 1) * 8 + (lane & 7);
    const int a_kadd     = (lane >> 4) * 8;
    const int b_row_lane = (lane >> 4) * 8 + (lane & 7);
    const int b_kadd     = ((lane >> 3) & 1) * 8;

    const int head  = blockIdx.y;
    const int node0 = blockIdx.x * NB;

    float c_reg[2][2][4];   // [mtile][rowhalf][joff]

    for (int l = 0; l < 2; ++l) {
        // ======== layer prologue ========
        const float* Wih_g = W_ih + (size_t)(l * N_HEADS + head) * (G_DIM * H_DIM);
        const float* Whh_g = W_hh + (size_t)(l * N_HEADS + head) * (G_DIM * H_DIM);

        // B tile, gate-interleave row permutation:
        // row = (wn<<6)|(t<<3)|(q<<1)|b ; g = ((t&1)<<1)|b ; j = (wn<<4)|(q<<2)|(t>>1)
        #pragma unroll 1
        for (int i = 0; i < 8; ++i) {
            int gidx = tid + i * THREADS;          // 4096 (row,k8) groups
            int row_out = gidx >> 4;
            int k8 = (gidx & 15) * 8;
            int tt = (row_out >> 3) & 7;
            int qq = (row_out >> 1) & 3;
            int bb = row_out & 1;
            int wnn = row_out >> 6;
            int g  = ((tt & 1) << 1) | bb;
            int jj = (wnn << 4) | (qq << 2) | (tt >> 1);
            const float* src = (k8 < 64) ? (Wih_g + (g * 64 + jj) * 64 + k8)
                                         : (Whh_g + (g * 64 + jj) * 64 + (k8 - 64));
            float v[8];
            float4 v0 = *(const float4*)(src);
            float4 v1 = *(const float4*)(src + 4);
            v[0]=v0.x; v[1]=v0.y; v[2]=v0.z; v[3]=v0.w;
            v[4]=v1.x; v[5]=v1.y; v[6]=v1.z; v[7]=v1.w;
            split8_store_f16(v, smem, SB_HI, SB_LO, swzoff(32, row_out, k8));
        }
        // bias (natural order g*64+j)
        if (tid < 256) {
            const float* bi = b_ih + (size_t)(l * N_HEADS + head) * G_DIM;
            const float* bh = b_hh + (size_t)(l * N_HEADS + head) * G_DIM;
            sbias[tid] = bi[tid] + bh[tid];
        }
        // h0 -> A h-region (k 64..127)
        {
            const float* hsrc = h0 + ((size_t)(head * 2 + l) * N_NODES + node0) * H_DIM;
            #pragma unroll
            for (int i = 0; i < 2; ++i) {
                int gidx = tid + i * THREADS;      // 1024 groups
                int n  = gidx >> 3;
                int k8 = (gidx & 7) * 8;
                float v[8];
                float4 v0 = *(const float4*)(hsrc + n * 64 + k8);
                float4 v1 = *(const float4*)(hsrc + n * 64 + k8 + 4);
                v[0]=v0.x; v[1]=v0.y; v[2]=v0.z; v[3]=v0.w;
                v[4]=v1.x; v[5]=v1.y; v[6]=v1.z; v[7]=v1.w;
                cvt8_store_f16(v, smem, SA, swzoff(16, n, 64 + k8));
            }
        }
        // c0 -> registers
        {
            const float* cbase = c0 + ((size_t)(head * 2 + l) * N_NODES + node0) * H_DIM;
            #pragma unroll
            for (int mt = 0; mt < 2; ++mt)
                #pragma unroll
                for (int rh = 0; rh < 2; ++rh) {
                    int rowL = mrow0 + mt * 16 + gid + rh * 8;
                    float4 v = *(const float4*)(cbase + (size_t)rowL * 64 + jg);
                    c_reg[mt][rh][0]=v.x; c_reg[mt][rh][1]=v.y;
                    c_reg[mt][rh][2]=v.z; c_reg[mt][rh][3]=v.w;
                }
        }
        const float* in_base = (l == 0) ? x : (g_hs0 + (size_t)head * T_LEN * N_NODES * H_DIM);
        float* out_base = ((l == 0) ? g_hs0 : g_hs1) + (size_t)head * T_LEN * N_NODES * H_DIM;

        // x_0 -> A x-region (direct LDG -> fp16)
        {
            const float* src0 = in_base + (size_t)node0 * H_DIM;
            #pragma unroll
            for (int i = 0; i < 2; ++i) {
                int gidx = tid + i * THREADS;
                int n = gidx >> 3, k8 = (gidx & 7) * 8;
                float v[8];
                float4 v0 = *(const float4*)(src0 + n * 64 + k8);
                float4 v1 = *(const float4*)(src0 + n * 64 + k8 + 4);
                v[0]=v0.x; v[1]=v0.y; v[2]=v0.z; v[3]=v0.w;
                v[4]=v1.x; v[5]=v1.y; v[6]=v1.z; v[7]=v1.w;
                cvt8_store_f16(v, smem, SA, swzoff(16, n, k8));
            }
        }
        __syncthreads();

        // ======== scan ========
        for (int t = 0; t < T_LEN; ++t) {
            // prefetch x_{t+1} into registers (LDG issues early, consumed post-sync)
            float xv[16];
            if (t + 1 < T_LEN) {
                const float* srcn = in_base + ((size_t)(t + 1) * N_NODES + node0) * H_DIM;
                #pragma unroll
                for (int i = 0; i < 2; ++i) {
                    int gidx = tid + i * THREADS;
                    int n = gidx >> 3, k8 = (gidx & 7) * 8;
                    float4 v0 = *(const float4*)(srcn + n * 64 + k8);
                    float4 v1 = *(const float4*)(srcn + n * 64 + k8 + 4);
                    xv[i*8+0]=v0.x; xv[i*8+1]=v0.y; xv[i*8+2]=v0.z; xv[i*8+3]=v0.w;
                    xv[i*8+4]=v1.x; xv[i*8+5]=v1.y; xv[i*8+6]=v1.z; xv[i*8+7]=v1.w;
                }
            }

            // accum, bias-initialized: col(nt,b): g=((nt&1)<<1)|b, j=jg+(nt>>1)
            float acc[2][8][4];
            #pragma unroll
            for (int nt = 0; nt < 8; ++nt) {
                float bv0 = sbias[(((nt & 1) << 1) | 0) * 64 + jg + (nt >> 1)];
                float bv1 = sbias[(((nt & 1) << 1) | 1) * 64 + jg + (nt >> 1)];
                #pragma unroll
                for (int mt = 0; mt < 2; ++mt) {
                    acc[mt][nt][0] = bv0; acc[mt][nt][1] = bv1;
                    acc[mt][nt][2] = bv0; acc[mt][nt][3] = bv1;
                }
            }

            // MMA: 2 passes (A * Bhi, A * Blo)
            #pragma unroll 1
            for (int kc = 0; kc < 8; ++kc) {
                int k0 = kc * 16;
                uint32_t af[2][4];
                #pragma unroll
                for (int mt = 0; mt < 2; ++mt) {
                    uint32_t off = swzoff(16, mrow0 + mt * 16 + a_row_lane, k0 + a_kadd);
                    ldsm4(af[mt], sbase + SA + off);
                }
                #pragma unroll
                for (int nt2 = 0; nt2 < 4; ++nt2) {
                    uint32_t off = swzoff(32, nbase + nt2 * 16 + b_row_lane, k0 + b_kadd);
                    uint32_t bh[4], bl[4];
                    ldsm4(bh, sbase + SB_HI + off);
                    ldsm4(bl, sbase + SB_LO + off);
                    #pragma unroll
                    for (int hf = 0; hf < 2; ++hf) {
                        uint32_t bh0 = bh[hf*2], bh1 = bh[hf*2+1];
                        uint32_t bl0 = bl[hf*2], bl1 = bl[hf*2+1];
                        #pragma unroll
                        for (int mt = 0; mt < 2; ++mt) {
                            float* c = acc[mt][nt2 * 2 + hf];
                            mma_f16(c, af[mt], bh0, bh1);
                            mma_f16(c, af[mt], bl0, bl1);
                        }
                    }
                }
            }
            __syncthreads();   // all ldmatrix reads of A done before overwrite

            // convert x_{t+1} into A x-region (from registers)
            if (t + 1 < T_LEN) {
                #pragma unroll
                for (int i = 0; i < 2; ++i) {
                    int gidx = tid + i * THREADS;
                    int n = gidx >> 3, k8 = (gidx & 7) * 8;
                    cvt8_store_f16(xv + i * 8, smem, SA, swzoff(16, n, k8));
                }
            }

            // epilogue: cell update; thread owns 8 rows x 4 hd (all 4 gates local)
            #pragma unroll
            for (int mt = 0; mt < 2; ++mt)
                #pragma unroll
                for (int rh = 0; rh < 2; ++rh) {
                    int rowL = mrow0 + mt * 16 + gid + rh * 8;
                    float hv[4];
                    #pragma unroll
                    for (int jo = 0; jo < 4; ++jo) {
                        float iv = acc[mt][2*jo  ][rh*2 + 0];
                        float fv = acc[mt][2*jo  ][rh*2 + 1];
                        float gv = acc[mt][2*jo+1][rh*2 + 0];
                        float ov = acc[mt][2*jo+1][rh*2 + 1];
                        float cc = sigf(fv) * c_reg[mt][rh][jo]
                                 + sigf(iv) * tanh_fast(gv);
                        c_reg[mt][rh][jo] = cc;
                        hv[jo] = sigf(ov) * tanh_fast(cc);
                    }
                    // GMEM h (fp32)
                    *(float4*)(out_base + ((size_t)t * N_NODES + node0 + rowL) * H_DIM + jg)
                        = make_float4(hv[0], hv[1], hv[2], hv[3]);
                    // SMEM A h-region (single fp16)
                    __half2 h0p = __floats2half2_rn(hv[0], hv[1]);
                    __half2 h1p = __floats2half2_rn(hv[2], hv[3]);
                    uint32_t off = swzoff(16, rowL, 64 + jg);
                    *(uint2*)(smem + SA + off) = make_uint2(*(uint32_t*)&h0p, *(uint32_t*)&h1p);
                }
            __syncthreads();
        }
        __threadfence();   // g_hs0 STGs visible before layer-1 reads
        __syncthreads();
    }
}

// out[o][n][hd] = sum_c hs1[c][n][hd] * conv_w[o][c] + conv_b[o]
__global__ __launch_bounds__(256)
void conv_kernel(const float* __restrict__ conv_w,
                 const float* __restrict__ conv_b,
                 float* __restrict__ out)
{
    __shared__ float sw[T_LEN * N_HEADS * T_LEN];
    __shared__ float sb[T_LEN];
    for (int i = threadIdx.x; i < T_LEN * N_HEADS * T_LEN; i += 256)
        sw[i] = conv_w[i];
    if (threadIdx.x < T_LEN) sb[threadIdx.x] = conv_b[threadIdx.x];
    __syncthreads();

    const size_t stride = (size_t)N_NODES * H_DIM;
    size_t nh4 = ((size_t)blockIdx.x * 256 + threadIdx.x) * 4;

    float acc[T_LEN][4];
    #pragma unroll
    for (int o = 0; o < T_LEN; ++o) {
        float b = sb[o];
        acc[o][0] = b; acc[o][1] = b; acc[o][2] = b; acc[o][3] = b;
    }
    #pragma unroll 4
    for (int c = 0; c < N_HEADS * T_LEN; ++c) {
        float4 v = *(const float4*)(g_hs1 + (size_t)c * stride + nh4);
        #pragma unroll
        for (int o = 0; o < T_LEN; ++o) {
            float w = sw[o * (N_HEADS * T_LEN) + c];
            acc[o][0] += v.x * w; acc[o][1] += v.y * w;
            acc[o][2] += v.z * w; acc[o][3] += v.w * w;
        }
    }
    #pragma unroll
    for (int o = 0; o < T_LEN; ++o)
        *(float4*)(out + (size_t)o * stride + nh4) =
            make_float4(acc[o][0], acc[o][1], acc[o][2], acc[o][3]);
}

extern "C" void kernel_launch(void* const* d_in, const int* in_sizes, int n_in,
                              void* d_out, int out_size)
{
    const float* x      = (const float*)d_in[0];
    const float* W_ih   = (const float*)d_in[1];
    const float* W_hh   = (const float*)d_in[2];
    const float* b_ih   = (const float*)d_in[3];
    const float* b_hh   = (const float*)d_in[4];
    const float* h0     = (const float*)d_in[5];
    const float* c0     = (const float*)d_in[6];
    const float* conv_w = (const float*)d_in[7];
    const float* conv_b = (const float*)d_in[8];
    float* out = (float*)d_out;

    cudaFuncSetAttribute(lstm_mma_kernel,
                         cudaFuncAttributeMaxDynamicSharedMemorySize, SMEM_TOTAL);

    dim3 grid(N_NODES / NB, N_HEADS);     // 128 x 8 = 1024 CTAs
    lstm_mma_kernel<<<grid, THREADS, SMEM_TOTAL>>>(x, W_ih, W_hh, b_ih, b_hh, h0, c0);

    conv_kernel<<<(N_NODES * H_DIM) / (4 * 256), 256>>>(conv_w, conv_b, out);
}

// round 6
// speedup vs baseline: 5.4969x; 1.4154x over previous
#include <cuda_runtime.h>
#include <cuda_fp16.h>
#include <cstdint>

#define T_LEN   12
#define N_HEADS 8
#define N_NODES 16384
#define H_DIM   64
#define G_DIM   256
#define NB      128          // nodes per CTA (= GEMM M)
#define THREADS 512

// ---- shared memory layout (bytes) ----
#define SA      0            // A tile: [128 rows][128 k] fp16 swizzled   (32768)
#define SB      32768        // B tile: [256 rows][128 k] fp16           (65536)
#define SBIAS   98304        // bias fp32 [256]                          (1024)
#define SMEM_TOTAL 99328

// Scratch: hs per layer, [head][t][node][hd], fp16
__device__ __half g_hs0[(size_t)N_HEADS * T_LEN * N_NODES * H_DIM];
__device__ __half g_hs1[(size_t)N_HEADS * T_LEN * N_NODES * H_DIM];

// swizzled byte offset in [R rows][128 k] fp16 tile; R8 = R/8, k = element idx
__device__ __forceinline__ uint32_t swzoff(int R8, int row, int k) {
    uint32_t off = (uint32_t)((((row >> 3) + (k >> 6) * R8) << 10)
                 + ((row & 7) << 7) + ((k & 63) << 1));
    return off ^ ((off >> 3) & 0x70);
}

__device__ __forceinline__ uint32_t smem_u32(const void* p) {
    uint32_t a;
    asm("{ .reg .u64 t; cvta.to.shared.u64 t, %1; cvt.u32.u64 %0, t; }" : "=r"(a) : "l"(p));
    return a;
}

__device__ __forceinline__ void ldsm4(uint32_t* r, uint32_t addr) {
    asm volatile("ldmatrix.sync.aligned.m8n8.x4.shared.b16 {%0,%1,%2,%3}, [%4];"
        : "=r"(r[0]), "=r"(r[1]), "=r"(r[2]), "=r"(r[3]) : "r"(addr));
}

__device__ __forceinline__ void mma_f16(float* c, const uint32_t* a,
                                        uint32_t b0, uint32_t b1) {
    asm volatile("mma.sync.aligned.m16n8k16.row.col.f32.f16.f16.f32 "
        "{%0,%1,%2,%3}, {%4,%5,%6,%7}, {%8,%9}, {%0,%1,%2,%3};"
        : "+f"(c[0]), "+f"(c[1]), "+f"(c[2]), "+f"(c[3])
        : "r"(a[0]), "r"(a[1]), "r"(a[2]), "r"(a[3]), "r"(b0), "r"(b1));
}

__device__ __forceinline__ float tanha(float x) {
    float y;
    asm("tanh.approx.f32 %0, %1;" : "=f"(y) : "f"(x));
    return y;
}
__device__ __forceinline__ float siga(float x) {
    return fmaf(tanha(0.5f * x), 0.5f, 0.5f);
}

// 8 fp32 -> 8 fp16, one 16B store into swizzled tile
__device__ __forceinline__ void cvt8_store_f16(const float* v, char* smem,
                                               int tile, uint32_t off) {
    uint32_t w[4];
    #pragma unroll
    for (int qq = 0; qq < 4; ++qq) {
        __half2 h = __floats2half2_rn(v[2 * qq], v[2 * qq + 1]);
        w[qq] = *(uint32_t*)&h;
    }
    *(uint4*)(smem + tile + off) = make_uint4(w[0], w[1], w[2], w[3]);
}

__global__ __launch_bounds__(THREADS, 1)
void lstm_mma_kernel(const float* __restrict__ x,
                     const float* __restrict__ W_ih,
                     const float* __restrict__ W_hh,
                     const float* __restrict__ b_ih,
                     const float* __restrict__ b_hh,
                     const float* __restrict__ h0,
                     const float* __restrict__ c0)
{
    extern __shared__ char smem[];
    const uint32_t sbase = smem_u32(smem);
    float* sbias = (float*)(smem + SBIAS);

    const int tid  = threadIdx.x;
    const int warp = tid >> 5;
    const int lane = tid & 31;
    const int wm = warp & 3;            // M-warp (4)
    const int wn = warp >> 2;           // N-warp (4)
    const int mrow0 = wm * 32;
    const int nbase = wn * 64;          // permuted-B row base
    const int gid = lane >> 2;
    const int q   = lane & 3;
    const int jg  = wn * 16 + q * 4;    // this thread's hd base (4 contiguous)

    const int a_row_lane = ((lane >> 3) & 1) * 8 + (lane & 7);
    const int a_kadd     = (lane >> 4) * 8;
    const int b_row_lane = (lane >> 4) * 8 + (lane & 7);
    const int b_kadd     = ((lane >> 3) & 1) * 8;

    const int head  = blockIdx.y;
    const int node0 = blockIdx.x * NB;

    float c_reg[2][2][4];   // [mtile][rowhalf][joff]

    for (int l = 0; l < 2; ++l) {
        // ======== layer prologue ========
        const float* Wih_g = W_ih + (size_t)(l * N_HEADS + head) * (G_DIM * H_DIM);
        const float* Whh_g = W_hh + (size_t)(l * N_HEADS + head) * (G_DIM * H_DIM);

        // B tile, gate-interleave row permutation:
        // row = (wn<<6)|(t<<3)|(q<<1)|b ; g = ((t&1)<<1)|b ; j = (wn<<4)|(q<<2)|(t>>1)
        #pragma unroll 1
        for (int i = 0; i < 8; ++i) {
            int gidx = tid + i * THREADS;          // 4096 (row,k8) groups
            int row_out = gidx >> 4;
            int k8 = (gidx & 15) * 8;
            int tt = (row_out >> 3) & 7;
            int qq = (row_out >> 1) & 3;
            int bb = row_out & 1;
            int wnn = row_out >> 6;
            int g  = ((tt & 1) << 1) | bb;
            int jj = (wnn << 4) | (qq << 2) | (tt >> 1);
            const float* src = (k8 < 64) ? (Wih_g + (g * 64 + jj) * 64 + k8)
                                         : (Whh_g + (g * 64 + jj) * 64 + (k8 - 64));
            float v[8];
            float4 v0 = *(const float4*)(src);
            float4 v1 = *(const float4*)(src + 4);
            v[0]=v0.x; v[1]=v0.y; v[2]=v0.z; v[3]=v0.w;
            v[4]=v1.x; v[5]=v1.y; v[6]=v1.z; v[7]=v1.w;
            cvt8_store_f16(v, smem, SB, swzoff(32, row_out, k8));
        }
        // bias (natural order g*64+j)
        if (tid < 256) {
            const float* bi = b_ih + (size_t)(l * N_HEADS + head) * G_DIM;
            const float* bh = b_hh + (size_t)(l * N_HEADS + head) * G_DIM;
            sbias[tid] = bi[tid] + bh[tid];
        }
        // h0 -> A h-region (k 64..127)
        {
            const float* hsrc = h0 + ((size_t)(head * 2 + l) * N_NODES + node0) * H_DIM;
            #pragma unroll
            for (int i = 0; i < 2; ++i) {
                int gidx = tid + i * THREADS;      // 1024 groups
                int n  = gidx >> 3;
                int k8 = (gidx & 7) * 8;
                float v[8];
                float4 v0 = *(const float4*)(hsrc + n * 64 + k8);
                float4 v1 = *(const float4*)(hsrc + n * 64 + k8 + 4);
                v[0]=v0.x; v[1]=v0.y; v[2]=v0.z; v[3]=v0.w;
                v[4]=v1.x; v[5]=v1.y; v[6]=v1.z; v[7]=v1.w;
                cvt8_store_f16(v, smem, SA, swzoff(16, n, 64 + k8));
            }
        }
        // c0 -> registers
        {
            const float* cbase = c0 + ((size_t)(head * 2 + l) * N_NODES + node0) * H_DIM;
            #pragma unroll
            for (int mt = 0; mt < 2; ++mt)
                #pragma unroll
                for (int rh = 0; rh < 2; ++rh) {
                    int rowL = mrow0 + mt * 16 + gid + rh * 8;
                    float4 v = *(const float4*)(cbase + (size_t)rowL * 64 + jg);
                    c_reg[mt][rh][0]=v.x; c_reg[mt][rh][1]=v.y;
                    c_reg[mt][rh][2]=v.z; c_reg[mt][rh][3]=v.w;
                }
        }
        const float* xin = x;   // layer-0 fp32 input
        const __half* hin = g_hs0 + (size_t)head * T_LEN * N_NODES * H_DIM;
        __half* out_base = ((l == 0) ? g_hs0 : g_hs1)
                         + (size_t)head * T_LEN * N_NODES * H_DIM;

        // x_0 -> A x-region
        if (l == 0) {
            const float* src0 = xin + (size_t)node0 * H_DIM;
            #pragma unroll
            for (int i = 0; i < 2; ++i) {
                int gidx = tid + i * THREADS;
                int n = gidx >> 3, k8 = (gidx & 7) * 8;
                float v[8];
                float4 v0 = *(const float4*)(src0 + n * 64 + k8);
                float4 v1 = *(const float4*)(src0 + n * 64 + k8 + 4);
                v[0]=v0.x; v[1]=v0.y; v[2]=v0.z; v[3]=v0.w;
                v[4]=v1.x; v[5]=v1.y; v[6]=v1.z; v[7]=v1.w;
                cvt8_store_f16(v, smem, SA, swzoff(16, n, k8));
            }
        } else {
            const __half* src0 = hin + (size_t)node0 * H_DIM;
            #pragma unroll
            for (int i = 0; i < 2; ++i) {
                int gidx = tid + i * THREADS;
                int n = gidx >> 3, k8 = (gidx & 7) * 8;
                uint4 v = *(const uint4*)(src0 + n * 64 + k8);   // 8 halves
                *(uint4*)(smem + SA + swzoff(16, n, k8)) = v;
            }
        }
        __syncthreads();

        // ======== scan ========
        for (int t = 0; t < T_LEN; ++t) {
            // prefetch x_{t+1} (registers; stored to SMEM after the post-MMA sync)
            float xv[16];
            uint4 xh[2];
            if (t + 1 < T_LEN) {
                if (l == 0) {
                    const float* srcn = xin + ((size_t)(t + 1) * N_NODES + node0) * H_DIM;
                    #pragma unroll
                    for (int i = 0; i < 2; ++i) {
                        int gidx = tid + i * THREADS;
                        int n = gidx >> 3, k8 = (gidx & 7) * 8;
                        float4 v0 = *(const float4*)(srcn + n * 64 + k8);
                        float4 v1 = *(const float4*)(srcn + n * 64 + k8 + 4);
                        xv[i*8+0]=v0.x; xv[i*8+1]=v0.y; xv[i*8+2]=v0.z; xv[i*8+3]=v0.w;
                        xv[i*8+4]=v1.x; xv[i*8+5]=v1.y; xv[i*8+6]=v1.z; xv[i*8+7]=v1.w;
                    }
                } else {
                    const __half* srcn = hin + ((size_t)(t + 1) * N_NODES + node0) * H_DIM;
                    #pragma unroll
                    for (int i = 0; i < 2; ++i) {
                        int gidx = tid + i * THREADS;
                        int n = gidx >> 3, k8 = (gidx & 7) * 8;
                        xh[i] = *(const uint4*)(srcn + n * 64 + k8);
                    }
                }
            }

            // accum, bias-initialized: col(nt,b): g=((nt&1)<<1)|b, j=jg+(nt>>1)
            float acc[2][8][4];
            #pragma unroll
            for (int nt = 0; nt < 8; ++nt) {
                float bv0 = sbias[(((nt & 1) << 1) | 0) * 64 + jg + (nt >> 1)];
                float bv1 = sbias[(((nt & 1) << 1) | 1) * 64 + jg + (nt >> 1)];
                #pragma unroll
                for (int mt = 0; mt < 2; ++mt) {
                    acc[mt][nt][0] = bv0; acc[mt][nt][1] = bv1;
                    acc[mt][nt][2] = bv0; acc[mt][nt][3] = bv1;
                }
            }

            // MMA: single pass
            #pragma unroll 1
            for (int kc = 0; kc < 8; ++kc) {
                int k0 = kc * 16;
                uint32_t af[2][4];
                #pragma unroll
                for (int mt = 0; mt < 2; ++mt) {
                    uint32_t off = swzoff(16, mrow0 + mt * 16 + a_row_lane, k0 + a_kadd);
                    ldsm4(af[mt], sbase + SA + off);
                }
                #pragma unroll
                for (int nt2 = 0; nt2 < 4; ++nt2) {
                    uint32_t off = swzoff(32, nbase + nt2 * 16 + b_row_lane, k0 + b_kadd);
                    uint32_t bh[4];
                    ldsm4(bh, sbase + SB + off);
                    #pragma unroll
                    for (int hf = 0; hf < 2; ++hf) {
                        #pragma unroll
                        for (int mt = 0; mt < 2; ++mt)
                            mma_f16(acc[mt][nt2 * 2 + hf], af[mt], bh[hf*2], bh[hf*2+1]);
                    }
                }
            }
            __syncthreads();   // all ldmatrix reads of A done before overwrite

            // store x_{t+1} into A x-region
            if (t + 1 < T_LEN) {
                if (l == 0) {
                    #pragma unroll
                    for (int i = 0; i < 2; ++i) {
                        int gidx = tid + i * THREADS;
                        int n = gidx >> 3, k8 = (gidx & 7) * 8;
                        cvt8_store_f16(xv + i * 8, smem, SA, swzoff(16, n, k8));
                    }
                } else {
                    #pragma unroll
                    for (int i = 0; i < 2; ++i) {
                        int gidx = tid + i * THREADS;
                        int n = gidx >> 3, k8 = (gidx & 7) * 8;
                        *(uint4*)(smem + SA + swzoff(16, n, k8)) = xh[i];
                    }
                }
            }

            // epilogue: cell update; thread owns 8 rows x 4 hd (all 4 gates local)
            #pragma unroll
            for (int mt = 0; mt < 2; ++mt)
                #pragma unroll
                for (int rh = 0; rh < 2; ++rh) {
                    int rowL = mrow0 + mt * 16 + gid + rh * 8;
                    float hv[4];
                    #pragma unroll
                    for (int jo = 0; jo < 4; ++jo) {
                        float iv = acc[mt][2*jo  ][rh*2 + 0];
                        float fv = acc[mt][2*jo  ][rh*2 + 1];
                        float gv = acc[mt][2*jo+1][rh*2 + 0];
                        float ov = acc[mt][2*jo+1][rh*2 + 1];
                        float cc = siga(fv) * c_reg[mt][rh][jo]
                                 + siga(iv) * tanha(gv);
                        c_reg[mt][rh][jo] = cc;
                        hv[jo] = siga(ov) * tanha(cc);
                    }
                    __half2 h0p = __floats2half2_rn(hv[0], hv[1]);
                    __half2 h1p = __floats2half2_rn(hv[2], hv[3]);
                    uint2 hp = make_uint2(*(uint32_t*)&h0p, *(uint32_t*)&h1p);
                    // GMEM h (fp16, same bits)
                    *(uint2*)(out_base + ((size_t)t * N_NODES + node0 + rowL) * H_DIM + jg) = hp;
                    // SMEM A h-region
                    *(uint2*)(smem + SA + swzoff(16, rowL, 64 + jg)) = hp;
                }
            __syncthreads();
        }
        __threadfence();
        __syncthreads();
    }
}

// out[o][n][hd] = sum_c hs1[c][n][hd] * conv_w[o][c] + conv_b[o]
__global__ __launch_bounds__(256)
void conv_kernel(const float* __restrict__ conv_w,
                 const float* __restrict__ conv_b,
                 float* __restrict__ out)
{
    __shared__ float sw[T_LEN * N_HEADS * T_LEN];
    __shared__ float sb[T_LEN];
    for (int i = threadIdx.x; i < T_LEN * N_HEADS * T_LEN; i += 256)
        sw[i] = conv_w[i];
    if (threadIdx.x < T_LEN) sb[threadIdx.x] = conv_b[threadIdx.x];
    __syncthreads();

    const size_t stride = (size_t)N_NODES * H_DIM;
    size_t nh4 = ((size_t)blockIdx.x * 256 + threadIdx.x) * 4;

    float acc[T_LEN][4];
    #pragma unroll
    for (int o = 0; o < T_LEN; ++o) {
        float b = sb[o];
        acc[o][0] = b; acc[o][1] = b; acc[o][2] = b; acc[o][3] = b;
    }
    #pragma unroll 4
    for (int c = 0; c < N_HEADS * T_LEN; ++c) {
        uint2 raw = *(const uint2*)(g_hs1 + (size_t)c * stride + nh4);
        float2 f0 = __half22float2(*(__half2*)&raw.x);
        float2 f1 = __half22float2(*(__half2*)&raw.y);
        #pragma unroll
        for (int o = 0; o < T_LEN; ++o) {
            float w = sw[o * (N_HEADS * T_LEN) + c];
            acc[o][0] += f0.x * w; acc[o][1] += f0.y * w;
            acc[o][2] += f1.x * w; acc[o][3] += f1.y * w;
        }
    }
    #pragma unroll
    for (int o = 0; o < T_LEN; ++o)
        *(float4*)(out + (size_t)o * stride + nh4) =
            make_float4(acc[o][0], acc[o][1], acc[o][2], acc[o][3]);
}

extern "C" void kernel_launch(void* const* d_in, const int* in_sizes, int n_in,
                              void* d_out, int out_size)
{
    const float* x      = (const float*)d_in[0];
    const float* W_ih   = (const float*)d_in[1];
    const float* W_hh   = (const float*)d_in[2];
    const float* b_ih   = (const float*)d_in[3];
    const float* b_hh   = (const float*)d_in[4];
    const float* h0     = (const float*)d_in[5];
    const float* c0     = (const float*)d_in[6];
    const float* conv_w = (const float*)d_in[7];
    const float* conv_b = (const float*)d_in[8];
    float* out = (float*)d_out;

    cudaFuncSetAttribute(lstm_mma_kernel,
                         cudaFuncAttributeMaxDynamicSharedMemorySize, SMEM_TOTAL);

    dim3 grid(N_NODES / NB, N_HEADS);     // 128 x 8 = 1024 CTAs
    lstm_mma_kernel<<<grid, THREADS, SMEM_TOTAL>>>(x, W_ih, W_hh, b_ih, b_hh, h0, c0);

    conv_kernel<<<(N_NODES * H_DIM) / (4 * 256), 256>>>(conv_w, conv_b, out);
}

// round 7
// speedup vs baseline: 6.3277x; 1.1511x over previous
#include <cuda_runtime.h>
#include <cuda_fp16.h>
#include <cstdint>

#define T_LEN   12
#define N_HEADS 8
#define N_NODES 16384
#define H_DIM   64
#define G_DIM   256
#define NB      64           // nodes per CTA (= GEMM M)
#define THREADS 256

// ---- shared memory layout (bytes) ----
#define SA0     0            // A tile buf0: [64 rows][128 k] fp16 swizzled (16384)
#define SA1     16384        // A tile buf1                                  (16384)
#define SB      32768        // B tile: [256 rows][128 k] fp16              (65536)
#define SBIAS   98304        // bias fp32 [256]                             (1024)
#define SMEM_TOTAL 99328

// Scratch: hs per layer, [head][t][node][hd], fp16
__device__ __half g_hs0[(size_t)N_HEADS * T_LEN * N_NODES * H_DIM];
__device__ __half g_hs1[(size_t)N_HEADS * T_LEN * N_NODES * H_DIM];

// swizzled byte offset in [R rows][128 k] fp16 tile; R8 = R/8, k = element idx
__device__ __forceinline__ uint32_t swzoff(int R8, int row, int k) {
    uint32_t off = (uint32_t)((((row >> 3) + (k >> 6) * R8) << 10)
                 + ((row & 7) << 7) + ((k & 63) << 1));
    return off ^ ((off >> 3) & 0x70);
}

__device__ __forceinline__ uint32_t smem_u32(const void* p) {
    uint32_t a;
    asm("{ .reg .u64 t; cvta.to.shared.u64 t, %1; cvt.u32.u64 %0, t; }" : "=r"(a) : "l"(p));
    return a;
}

__device__ __forceinline__ void ldsm4(uint32_t* r, uint32_t addr) {
    asm volatile("ldmatrix.sync.aligned.m8n8.x4.shared.b16 {%0,%1,%2,%3}, [%4];"
        : "=r"(r[0]), "=r"(r[1]), "=r"(r[2]), "=r"(r[3]) : "r"(addr));
}

__device__ __forceinline__ void mma_f16(float* c, const uint32_t* a,
                                        uint32_t b0, uint32_t b1) {
    asm volatile("mma.sync.aligned.m16n8k16.row.col.f32.f16.f16.f32 "
        "{%0,%1,%2,%3}, {%4,%5,%6,%7}, {%8,%9}, {%0,%1,%2,%3};"
        : "+f"(c[0]), "+f"(c[1]), "+f"(c[2]), "+f"(c[3])
        : "r"(a[0]), "r"(a[1]), "r"(a[2]), "r"(a[3]), "r"(b0), "r"(b1));
}

__device__ __forceinline__ float tanha(float x) {
    float y;
    asm("tanh.approx.f32 %0, %1;" : "=f"(y) : "f"(x));
    return y;
}
__device__ __forceinline__ float siga(float x) {
    return fmaf(tanha(0.5f * x), 0.5f, 0.5f);
}

// 8 fp32 -> 8 fp16, one 16B store into swizzled tile
__device__ __forceinline__ void cvt8_store_f16(const float* v, char* smem,
                                               int tile, uint32_t off) {
    uint32_t w[4];
    #pragma unroll
    for (int qq = 0; qq < 4; ++qq) {
        __half2 h = __floats2half2_rn(v[2 * qq], v[2 * qq + 1]);
        w[qq] = *(uint32_t*)&h;
    }
    *(uint4*)(smem + tile + off) = make_uint4(w[0], w[1], w[2], w[3]);
}

__global__ __launch_bounds__(THREADS, 2)
void lstm_mma_kernel(const float* __restrict__ x,
                     const float* __restrict__ W_ih,
                     const float* __restrict__ W_hh,
                     const float* __restrict__ b_ih,
                     const float* __restrict__ b_hh,
                     const float* __restrict__ h0,
                     const float* __restrict__ c0)
{
    extern __shared__ char smem[];
    const uint32_t sbase = smem_u32(smem);
    float* sbias = (float*)(smem + SBIAS);

    const int tid  = threadIdx.x;
    const int warp = tid >> 5;
    const int lane = tid & 31;
    const int wm = warp & 1;            // M-warp (2)
    const int wn = warp >> 1;           // N-warp (4)
    const int mrow0 = wm * 32;
    const int nbase = wn * 64;          // permuted-B row base
    const int gid = lane >> 2;
    const int q   = lane & 3;
    const int jg  = wn * 16 + q * 4;    // this thread's hd base (4 contiguous)

    const int a_row_lane = ((lane >> 3) & 1) * 8 + (lane & 7);
    const int a_kadd     = (lane >> 4) * 8;
    const int b_row_lane = (lane >> 4) * 8 + (lane & 7);
    const int b_kadd     = ((lane >> 3) & 1) * 8;

    const int head  = blockIdx.y;
    const int node0 = blockIdx.x * NB;

    float c_reg[2][2][4];   // [mtile][rowhalf][joff]

    for (int l = 0; l < 2; ++l) {
        // ======== layer prologue ========
        const float* Wih_g = W_ih + (size_t)(l * N_HEADS + head) * (G_DIM * H_DIM);
        const float* Whh_g = W_hh + (size_t)(l * N_HEADS + head) * (G_DIM * H_DIM);

        // B tile, gate-interleave row permutation:
        // row = (wn<<6)|(t<<3)|(q<<1)|b ; g = ((t&1)<<1)|b ; j = (wn<<4)|(q<<2)|(t>>1)
        #pragma unroll 1
        for (int i = 0; i < 16; ++i) {
            int gidx = tid + i * THREADS;          // 4096 (row,k8) groups
            int row_out = gidx >> 4;
            int k8 = (gidx & 15) * 8;
            int tt = (row_out >> 3) & 7;
            int qq = (row_out >> 1) & 3;
            int bb = row_out & 1;
            int wnn = row_out >> 6;
            int g  = ((tt & 1) << 1) | bb;
            int jj = (wnn << 4) | (qq << 2) | (tt >> 1);
            const float* src = (k8 < 64) ? (Wih_g + (g * 64 + jj) * 64 + k8)
                                         : (Whh_g + (g * 64 + jj) * 64 + (k8 - 64));
            float v[8];
            float4 v0 = *(const float4*)(src);
            float4 v1 = *(const float4*)(src + 4);
            v[0]=v0.x; v[1]=v0.y; v[2]=v0.z; v[3]=v0.w;
            v[4]=v1.x; v[5]=v1.y; v[6]=v1.z; v[7]=v1.w;
            cvt8_store_f16(v, smem, SB, swzoff(32, row_out, k8));
        }
        // bias (natural order g*64+j)
        {
            const float* bi = b_ih + (size_t)(l * N_HEADS + head) * G_DIM;
            const float* bh = b_hh + (size_t)(l * N_HEADS + head) * G_DIM;
            sbias[tid] = bi[tid] + bh[tid];
        }
        // h0 -> A[0] h-region (k 64..127)
        {
            const float* hsrc = h0 + ((size_t)(head * 2 + l) * N_NODES + node0) * H_DIM;
            #pragma unroll
            for (int i = 0; i < 2; ++i) {
                int gidx = tid + i * THREADS;      // 512 groups
                int n  = gidx >> 3;
                int k8 = (gidx & 7) * 8;
                float v[8];
                float4 v0 = *(const float4*)(hsrc + n * 64 + k8);
                float4 v1 = *(const float4*)(hsrc + n * 64 + k8 + 4);
                v[0]=v0.x; v[1]=v0.y; v[2]=v0.z; v[3]=v0.w;
                v[4]=v1.x; v[5]=v1.y; v[6]=v1.z; v[7]=v1.w;
                cvt8_store_f16(v, smem, SA0, swzoff(8, n, 64 + k8));
            }
        }
        // c0 -> registers
        {
            const float* cbase = c0 + ((size_t)(head * 2 + l) * N_NODES + node0) * H_DIM;
            #pragma unroll
            for (int mt = 0; mt < 2; ++mt)
                #pragma unroll
                for (int rh = 0; rh < 2; ++rh) {
                    int rowL = mrow0 + mt * 16 + gid + rh * 8;
                    float4 v = *(const float4*)(cbase + (size_t)rowL * 64 + jg);
                    c_reg[mt][rh][0]=v.x; c_reg[mt][rh][1]=v.y;
                    c_reg[mt][rh][2]=v.z; c_reg[mt][rh][3]=v.w;
                }
        }
        const float* xin = x;
        const __half* hin = g_hs0 + (size_t)head * T_LEN * N_NODES * H_DIM;
        __half* out_base = ((l == 0) ? g_hs0 : g_hs1)
                         + (size_t)head * T_LEN * N_NODES * H_DIM;

        // x_0 -> A[0] x-region
        if (l == 0) {
            const float* src0 = xin + (size_t)node0 * H_DIM;
            #pragma unroll
            for (int i = 0; i < 2; ++i) {
                int gidx = tid + i * THREADS;
                int n = gidx >> 3, k8 = (gidx & 7) * 8;
                float v[8];
                float4 v0 = *(const float4*)(src0 + n * 64 + k8);
                float4 v1 = *(const float4*)(src0 + n * 64 + k8 + 4);
                v[0]=v0.x; v[1]=v0.y; v[2]=v0.z; v[3]=v0.w;
                v[4]=v1.x; v[5]=v1.y; v[6]=v1.z; v[7]=v1.w;
                cvt8_store_f16(v, smem, SA0, swzoff(8, n, k8));
            }
        } else {
            const __half* src0 = hin + (size_t)node0 * H_DIM;
            #pragma unroll
            for (int i = 0; i < 2; ++i) {
                int gidx = tid + i * THREADS;
                int n = gidx >> 3, k8 = (gidx & 7) * 8;
                uint4 v = *(const uint4*)(src0 + n * 64 + k8);   // 8 halves
                *(uint4*)(smem + SA0 + swzoff(8, n, k8)) = v;
            }
        }
        __syncthreads();

        // ======== scan (double-buffered A, ONE sync per step) ========
        for (int t = 0; t < T_LEN; ++t) {
            const int SAc = (t & 1) ? SA1 : SA0;   // MMA reads
            const int SAn = (t & 1) ? SA0 : SA1;   // epilogue/staging writes

            // prefetch x_{t+1} into registers
            float xv[16];
            uint4 xh[2];
            if (t + 1 < T_LEN) {
                if (l == 0) {
                    const float* srcn = xin + ((size_t)(t + 1) * N_NODES + node0) * H_DIM;
                    #pragma unroll
                    for (int i = 0; i < 2; ++i) {
                        int gidx = tid + i * THREADS;
                        int n = gidx >> 3, k8 = (gidx & 7) * 8;
                        float4 v0 = *(const float4*)(srcn + n * 64 + k8);
                        float4 v1 = *(const float4*)(srcn + n * 64 + k8 + 4);
                        xv[i*8+0]=v0.x; xv[i*8+1]=v0.y; xv[i*8+2]=v0.z; xv[i*8+3]=v0.w;
                        xv[i*8+4]=v1.x; xv[i*8+5]=v1.y; xv[i*8+6]=v1.z; xv[i*8+7]=v1.w;
                    }
                } else {
                    const __half* srcn = hin + ((size_t)(t + 1) * N_NODES + node0) * H_DIM;
                    #pragma unroll
                    for (int i = 0; i < 2; ++i) {
                        int gidx = tid + i * THREADS;
                        int n = gidx >> 3, k8 = (gidx & 7) * 8;
                        xh[i] = *(const uint4*)(srcn + n * 64 + k8);
                    }
                }
            }

            // accum, bias-initialized: col(nt,b): g=((nt&1)<<1)|b, j=jg+(nt>>1)
            float acc[2][8][4];
            #pragma unroll
            for (int nt = 0; nt < 8; ++nt) {
                float bv0 = sbias[(((nt & 1) << 1) | 0) * 64 + jg + (nt >> 1)];
                float bv1 = sbias[(((nt & 1) << 1) | 1) * 64 + jg + (nt >> 1)];
                #pragma unroll
                for (int mt = 0; mt < 2; ++mt) {
                    acc[mt][nt][0] = bv0; acc[mt][nt][1] = bv1;
                    acc[mt][nt][2] = bv0; acc[mt][nt][3] = bv1;
                }
            }

            // MMA: single pass over K=128 (reads A[cur])
            #pragma unroll 1
            for (int kc = 0; kc < 8; ++kc) {
                int k0 = kc * 16;
                uint32_t af[2][4];
                #pragma unroll
                for (int mt = 0; mt < 2; ++mt) {
                    uint32_t off = swzoff(8, mrow0 + mt * 16 + a_row_lane, k0 + a_kadd);
                    ldsm4(af[mt], sbase + SAc + off);
                }
                #pragma unroll
                for (int nt2 = 0; nt2 < 4; ++nt2) {
                    uint32_t off = swzoff(32, nbase + nt2 * 16 + b_row_lane, k0 + b_kadd);
                    uint32_t bh[4];
                    ldsm4(bh, sbase + SB + off);
                    #pragma unroll
                    for (int hf = 0; hf < 2; ++hf) {
                        #pragma unroll
                        for (int mt = 0; mt < 2; ++mt)
                            mma_f16(acc[mt][nt2 * 2 + hf], af[mt], bh[hf*2], bh[hf*2+1]);
                    }
                }
            }

            // store x_{t+1} into A[nxt] x-region (no sync needed: different buffer)
            if (t + 1 < T_LEN) {
                if (l == 0) {
                    #pragma unroll
                    for (int i = 0; i < 2; ++i) {
                        int gidx = tid + i * THREADS;
                        int n = gidx >> 3, k8 = (gidx & 7) * 8;
                        cvt8_store_f16(xv + i * 8, smem, SAn, swzoff(8, n, k8));
                    }
                } else {
                    #pragma unroll
                    for (int i = 0; i < 2; ++i) {
                        int gidx = tid + i * THREADS;
                        int n = gidx >> 3, k8 = (gidx & 7) * 8;
                        *(uint4*)(smem + SAn + swzoff(8, n, k8)) = xh[i];
                    }
                }
            }

            // epilogue: cell update; h -> GMEM + A[nxt] h-region
            #pragma unroll
            for (int mt = 0; mt < 2; ++mt)
                #pragma unroll
                for (int rh = 0; rh < 2; ++rh) {
                    int rowL = mrow0 + mt * 16 + gid + rh * 8;
                    float hv[4];
                    #pragma unroll
                    for (int jo = 0; jo < 4; ++jo) {
                        float iv = acc[mt][2*jo  ][rh*2 + 0];
                        float fv = acc[mt][2*jo  ][rh*2 + 1];
                        float gv = acc[mt][2*jo+1][rh*2 + 0];
                        float ov = acc[mt][2*jo+1][rh*2 + 1];
                        float cc = siga(fv) * c_reg[mt][rh][jo]
                                 + siga(iv) * tanha(gv);
                        c_reg[mt][rh][jo] = cc;
                        hv[jo] = siga(ov) * tanha(cc);
                    }
                    __half2 h0p = __floats2half2_rn(hv[0], hv[1]);
                    __half2 h1p = __floats2half2_rn(hv[2], hv[3]);
                    uint2 hp = make_uint2(*(uint32_t*)&h0p, *(uint32_t*)&h1p);
                    *(uint2*)(out_base + ((size_t)t * N_NODES + node0 + rowL) * H_DIM + jg) = hp;
                    *(uint2*)(smem + SAn + swzoff(8, rowL, 64 + jg)) = hp;
                }
            __syncthreads();   // all A[nxt] writes visible before next step's MMA
        }
        __threadfence();   // g_hs0 visible before layer-1 reads
        __syncthreads();
    }
}

// out[o][n][hd] = sum_c hs1[c][n][hd] * conv_w[o][c] + conv_b[o]
__global__ __launch_bounds__(256)
void conv_kernel(const float* __restrict__ conv_w,
                 const float* __restrict__ conv_b,
                 float* __restrict__ out)
{
    __shared__ float sw[T_LEN * N_HEADS * T_LEN];
    __shared__ float sb[T_LEN];
    for (int i = threadIdx.x; i < T_LEN * N_HEADS * T_LEN; i += 256)
        sw[i] = conv_w[i];
    if (threadIdx.x < T_LEN) sb[threadIdx.x] = conv_b[threadIdx.x];
    __syncthreads();

    const size_t stride = (size_t)N_NODES * H_DIM;
    size_t nh4 = ((size_t)blockIdx.x * 256 + threadIdx.x) * 4;

    float acc[T_LEN][4];
    #pragma unroll
    for (int o = 0; o < T_LEN; ++o) {
        float b = sb[o];
        acc[o][0] = b; acc[o][1] = b; acc[o][2] = b; acc[o][3] = b;
    }
    #pragma unroll 4
    for (int c = 0; c < N_HEADS * T_LEN; ++c) {
        uint2 raw = *(const uint2*)(g_hs1 + (size_t)c * stride + nh4);
        float2 f0 = __half22float2(*(__half2*)&raw.x);
        float2 f1 = __half22float2(*(__half2*)&raw.y);
        #pragma unroll
        for (int o = 0; o < T_LEN; ++o) {
            float w = sw[o * (N_HEADS * T_LEN) + c];
            acc[o][0] += f0.x * w; acc[o][1] += f0.y * w;
            acc[o][2] += f1.x * w; acc[o][3] += f1.y * w;
        }
    }
    #pragma unroll
    for (int o = 0; o < T_LEN; ++o)
        *(float4*)(out + (size_t)o * stride + nh4) =
            make_float4(acc[o][0], acc[o][1], acc[o][2], acc[o][3]);
}

extern "C" void kernel_launch(void* const* d_in, const int* in_sizes, int n_in,
                              void* d_out, int out_size)
{
    const float* x      = (const float*)d_in[0];
    const float* W_ih   = (const float*)d_in[1];
    const float* W_hh   = (const float*)d_in[2];
    const float* b_ih   = (const float*)d_in[3];
    const float* b_hh   = (const float*)d_in[4];
    const float* h0     = (const float*)d_in[5];
    const float* c0     = (const float*)d_in[6];
    const float* conv_w = (const float*)d_in[7];
    const float* conv_b = (const float*)d_in[8];
    float* out = (float*)d_out;

    cudaFuncSetAttribute(lstm_mma_kernel,
                         cudaFuncAttributeMaxDynamicSharedMemorySize, SMEM_TOTAL);

    dim3 grid(N_NODES / NB, N_HEADS);     // 256 x 8 = 2048 CTAs
    lstm_mma_kernel<<<grid, THREADS, SMEM_TOTAL>>>(x, W_ih, W_hh, b_ih, b_hh, h0, c0);

    conv_kernel<<<(N_NODES * H_DIM) / (4 * 256), 256>>>(conv_w, conv_b, out);
}

// round 8
// speedup vs baseline: 6.8464x; 1.0820x over previous
#include <cuda_runtime.h>
#include <cuda_fp16.h>
#include <cstdint>

#define T_LEN   12
#define N_HEADS 8
#define N_NODES 16384
#define H_DIM   64
#define G_DIM   256
#define NB      64           // nodes per CTA (= GEMM M)
#define THREADS 256

// ---- shared memory layout (bytes) ----
#define SA0     0            // A tile buf0: [64 rows][128 k] fp16 swizzled (16384)
#define SA1     16384        // A tile buf1                                  (16384)
#define SB      32768        // B tile: [256 rows][128 k] fp16              (65536)
#define SBIAS   98304        // bias fp32 [256]                             (1024)
#define SMEM_TOTAL 99328

// Scratch: hs per layer, [head][t][node][hd], fp16
__device__ __half g_hs0[(size_t)N_HEADS * T_LEN * N_NODES * H_DIM];
__device__ __half g_hs1[(size_t)N_HEADS * T_LEN * N_NODES * H_DIM];

__device__ __forceinline__ uint32_t swzoff(int R8, int row, int k) {
    uint32_t off = (uint32_t)((((row >> 3) + (k >> 6) * R8) << 10)
                 + ((row & 7) << 7) + ((k & 63) << 1));
    return off ^ ((off >> 3) & 0x70);
}

__device__ __forceinline__ uint32_t smem_u32(const void* p) {
    uint32_t a;
    asm("{ .reg .u64 t; cvta.to.shared.u64 t, %1; cvt.u32.u64 %0, t; }" : "=r"(a) : "l"(p));
    return a;
}

__device__ __forceinline__ void ldsm4(uint32_t* r, uint32_t addr) {
    asm volatile("ldmatrix.sync.aligned.m8n8.x4.shared.b16 {%0,%1,%2,%3}, [%4];"
        : "=r"(r[0]), "=r"(r[1]), "=r"(r[2]), "=r"(r[3]) : "r"(addr));
}

__device__ __forceinline__ void mma_f16(float* c, const uint32_t* a,
                                        uint32_t b0, uint32_t b1) {
    asm volatile("mma.sync.aligned.m16n8k16.row.col.f32.f16.f16.f32 "
        "{%0,%1,%2,%3}, {%4,%5,%6,%7}, {%8,%9}, {%0,%1,%2,%3};"
        : "+f"(c[0]), "+f"(c[1]), "+f"(c[2]), "+f"(c[3])
        : "r"(a[0]), "r"(a[1]), "r"(a[2]), "r"(a[3]), "r"(b0), "r"(b1));
}

__device__ __forceinline__ float tanha(float x) {
    float y;
    asm("tanh.approx.f32 %0, %1;" : "=f"(y) : "f"(x));
    return y;
}
__device__ __forceinline__ float siga(float x) {
    return fmaf(tanha(0.5f * x), 0.5f, 0.5f);
}
// two tanh in one MUFU op (fp16 eval)
__device__ __forceinline__ float2 tanh2(float a, float b) {
    __half2 hx = __floats2half2_rn(a, b);
    uint32_t xr = *(uint32_t*)&hx, yr;
    asm("tanh.approx.f16x2 %0, %1;" : "=r"(yr) : "r"(xr));
    return __half22float2(*(__half2*)&yr);
}

// 8 fp32 -> 8 fp16, one 16B store into swizzled tile
__device__ __forceinline__ void cvt8_store_f16(const float* v, char* smem,
                                               int tile, uint32_t off) {
    uint32_t w[4];
    #pragma unroll
    for (int qq = 0; qq < 4; ++qq) {
        __half2 h = __floats2half2_rn(v[2 * qq], v[2 * qq + 1]);
        w[qq] = *(uint32_t*)&h;
    }
    *(uint4*)(smem + tile + off) = make_uint4(w[0], w[1], w[2], w[3]);
}

__global__ __launch_bounds__(THREADS, 2)
void lstm_mma_kernel(const float* __restrict__ x,
                     const float* __restrict__ W_ih,
                     const float* __restrict__ W_hh,
                     const float* __restrict__ b_ih,
                     const float* __restrict__ b_hh,
                     const float* __restrict__ h0,
                     const float* __restrict__ c0)
{
    extern __shared__ char smem[];
    const uint32_t sbase = smem_u32(smem);
    float* sbias = (float*)(smem + SBIAS);

    const int tid  = threadIdx.x;
    const int warp = tid >> 5;
    const int lane = tid & 31;
    const int wm = warp & 1;            // M-warp (2)
    const int wn = warp >> 1;           // N-warp (4)
    const int mrow0 = wm * 32;
    const int nbase = wn * 64;          // permuted-B row base
    const int gid = lane >> 2;
    const int q   = lane & 3;
    const int jg  = wn * 16 + q * 4;    // this thread's hd base (4 contiguous)

    const int a_row_lane = ((lane >> 3) & 1) * 8 + (lane & 7);
    const int a_kadd     = (lane >> 4) * 8;
    const int b_row_lane = (lane >> 4) * 8 + (lane & 7);
    const int b_kadd     = ((lane >> 3) & 1) * 8;

    const int head  = blockIdx.y;
    const int node0 = blockIdx.x * NB;

    float c_reg[2][2][4];   // [mtile][rowhalf][joff]

    for (int l = 0; l < 2; ++l) {
        // ======== layer prologue ========
        const float* Wih_g = W_ih + (size_t)(l * N_HEADS + head) * (G_DIM * H_DIM);
        const float* Whh_g = W_hh + (size_t)(l * N_HEADS + head) * (G_DIM * H_DIM);

        // B tile, gate-interleave row permutation:
        // row = (wn<<6)|(t<<3)|(q<<1)|b ; g = ((t&1)<<1)|b ; j = (wn<<4)|(q<<2)|(t>>1)
        #pragma unroll 1
        for (int i = 0; i < 16; ++i) {
            int gidx = tid + i * THREADS;          // 4096 (row,k8) groups
            int row_out = gidx >> 4;
            int k8 = (gidx & 15) * 8;
            int tt = (row_out >> 3) & 7;
            int qq = (row_out >> 1) & 3;
            int bb = row_out & 1;
            int wnn = row_out >> 6;
            int g  = ((tt & 1) << 1) | bb;
            int jj = (wnn << 4) | (qq << 2) | (tt >> 1);
            const float* src = (k8 < 64) ? (Wih_g + (g * 64 + jj) * 64 + k8)
                                         : (Whh_g + (g * 64 + jj) * 64 + (k8 - 64));
            float v[8];
            float4 v0 = *(const float4*)(src);
            float4 v1 = *(const float4*)(src + 4);
            v[0]=v0.x; v[1]=v0.y; v[2]=v0.z; v[3]=v0.w;
            v[4]=v1.x; v[5]=v1.y; v[6]=v1.z; v[7]=v1.w;
            cvt8_store_f16(v, smem, SB, swzoff(32, row_out, k8));
        }
        // bias
        {
            const float* bi = b_ih + (size_t)(l * N_HEADS + head) * G_DIM;
            const float* bh = b_hh + (size_t)(l * N_HEADS + head) * G_DIM;
            sbias[tid] = bi[tid] + bh[tid];
        }
        // h0 -> A[0] h-region (k 64..127)
        {
            const float* hsrc = h0 + ((size_t)(head * 2 + l) * N_NODES + node0) * H_DIM;
            #pragma unroll
            for (int i = 0; i < 2; ++i) {
                int gidx = tid + i * THREADS;
                int n  = gidx >> 3;
                int k8 = (gidx & 7) * 8;
                float v[8];
                float4 v0 = *(const float4*)(hsrc + n * 64 + k8);
                float4 v1 = *(const float4*)(hsrc + n * 64 + k8 + 4);
                v[0]=v0.x; v[1]=v0.y; v[2]=v0.z; v[3]=v0.w;
                v[4]=v1.x; v[5]=v1.y; v[6]=v1.z; v[7]=v1.w;
                cvt8_store_f16(v, smem, SA0, swzoff(8, n, 64 + k8));
            }
        }
        // c0 -> registers
        {
            const float* cbase = c0 + ((size_t)(head * 2 + l) * N_NODES + node0) * H_DIM;
            #pragma unroll
            for (int mt = 0; mt < 2; ++mt)
                #pragma unroll
                for (int rh = 0; rh < 2; ++rh) {
                    int rowL = mrow0 + mt * 16 + gid + rh * 8;
                    float4 v = *(const float4*)(cbase + (size_t)rowL * 64 + jg);
                    c_reg[mt][rh][0]=v.x; c_reg[mt][rh][1]=v.y;
                    c_reg[mt][rh][2]=v.z; c_reg[mt][rh][3]=v.w;
                }
        }
        const float* xin = x;
        const __half* hin = g_hs0 + (size_t)head * T_LEN * N_NODES * H_DIM;
        __half* out_base = ((l == 0) ? g_hs0 : g_hs1)
                         + (size_t)head * T_LEN * N_NODES * H_DIM;

        // x_0 -> A[0] x-region
        if (l == 0) {
            const float* src0 = xin + (size_t)node0 * H_DIM;
            #pragma unroll
            for (int i = 0; i < 2; ++i) {
                int gidx = tid + i * THREADS;
                int n = gidx >> 3, k8 = (gidx & 7) * 8;
                float v[8];
                float4 v0 = *(const float4*)(src0 + n * 64 + k8);
                float4 v1 = *(const float4*)(src0 + n * 64 + k8 + 4);
                v[0]=v0.x; v[1]=v0.y; v[2]=v0.z; v[3]=v0.w;
                v[4]=v1.x; v[5]=v1.y; v[6]=v1.z; v[7]=v1.w;
                cvt8_store_f16(v, smem, SA0, swzoff(8, n, k8));
            }
        } else {
            const __half* src0 = hin + (size_t)node0 * H_DIM;
            #pragma unroll
            for (int i = 0; i < 2; ++i) {
                int gidx = tid + i * THREADS;
                int n = gidx >> 3, k8 = (gidx & 7) * 8;
                uint4 v = *(const uint4*)(src0 + n * 64 + k8);
                *(uint4*)(smem + SA0 + swzoff(8, n, k8)) = v;
            }
        }
        __syncthreads();

        // hoist Whh B-fragments (kc = 5..7) into registers for the whole scan
        uint32_t bfr[3][4][4];
        #pragma unroll
        for (int kh = 0; kh < 3; ++kh)
            #pragma unroll
            for (int nt2 = 0; nt2 < 4; ++nt2) {
                uint32_t off = swzoff(32, nbase + nt2 * 16 + b_row_lane,
                                      (5 + kh) * 16 + b_kadd);
                ldsm4(bfr[kh][nt2], sbase + SB + off);
            }

        // ======== scan (double-buffered A, ONE sync per step) ========
        for (int t = 0; t < T_LEN; ++t) {
            const int SAc = (t & 1) ? SA1 : SA0;   // MMA reads
            const int SAn = (t & 1) ? SA0 : SA1;   // epilogue/staging writes

            // prefetch x_{t+1} into registers
            float xv[16];
            uint4 xh[2];
            if (t + 1 < T_LEN) {
                if (l == 0) {
                    const float* srcn = xin + ((size_t)(t + 1) * N_NODES + node0) * H_DIM;
                    #pragma unroll
                    for (int i = 0; i < 2; ++i) {
                        int gidx = tid + i * THREADS;
                        int n = gidx >> 3, k8 = (gidx & 7) * 8;
                        float4 v0 = *(const float4*)(srcn + n * 64 + k8);
                        float4 v1 = *(const float4*)(srcn + n * 64 + k8 + 4);
                        xv[i*8+0]=v0.x; xv[i*8+1]=v0.y; xv[i*8+2]=v0.z; xv[i*8+3]=v0.w;
                        xv[i*8+4]=v1.x; xv[i*8+5]=v1.y; xv[i*8+6]=v1.z; xv[i*8+7]=v1.w;
                    }
                } else {
                    const __half* srcn = hin + ((size_t)(t + 1) * N_NODES + node0) * H_DIM;
                    #pragma unroll
                    for (int i = 0; i < 2; ++i) {
                        int gidx = tid + i * THREADS;
                        int n = gidx >> 3, k8 = (gidx & 7) * 8;
                        xh[i] = *(const uint4*)(srcn + n * 64 + k8);
                    }
                }
            }

            // accum, bias-initialized
            float acc[2][8][4];
            #pragma unroll
            for (int nt = 0; nt < 8; ++nt) {
                float bv0 = sbias[(((nt & 1) << 1) | 0) * 64 + jg + (nt >> 1)];
                float bv1 = sbias[(((nt & 1) << 1) | 1) * 64 + jg + (nt >> 1)];
                #pragma unroll
                for (int mt = 0; mt < 2; ++mt) {
                    acc[mt][nt][0] = bv0; acc[mt][nt][1] = bv1;
                    acc[mt][nt][2] = bv0; acc[mt][nt][3] = bv1;
                }
            }

            // MMA part 1: kc 0..4 with B from SMEM
            #pragma unroll
            for (int kc = 0; kc < 5; ++kc) {
                int k0 = kc * 16;
                uint32_t af[2][4];
                #pragma unroll
                for (int mt = 0; mt < 2; ++mt) {
                    uint32_t off = swzoff(8, mrow0 + mt * 16 + a_row_lane, k0 + a_kadd);
                    ldsm4(af[mt], sbase + SAc + off);
                }
                #pragma unroll
                for (int nt2 = 0; nt2 < 4; ++nt2) {
                    uint32_t off = swzoff(32, nbase + nt2 * 16 + b_row_lane, k0 + b_kadd);
                    uint32_t bh[4];
                    ldsm4(bh, sbase + SB + off);
                    #pragma unroll
                    for (int hf = 0; hf < 2; ++hf)
                        #pragma unroll
                        for (int mt = 0; mt < 2; ++mt)
                            mma_f16(acc[mt][nt2 * 2 + hf], af[mt], bh[hf*2], bh[hf*2+1]);
                }
            }
            // MMA part 2: kc 5..7 with hoisted B fragments
            #pragma unroll
            for (int kh = 0; kh < 3; ++kh) {
                int k0 = (5 + kh) * 16;
                uint32_t af[2][4];
                #pragma unroll
                for (int mt = 0; mt < 2; ++mt) {
                    uint32_t off = swzoff(8, mrow0 + mt * 16 + a_row_lane, k0 + a_kadd);
                    ldsm4(af[mt], sbase + SAc + off);
                }
                #pragma unroll
                for (int nt2 = 0; nt2 < 4; ++nt2)
                    #pragma unroll
                    for (int hf = 0; hf < 2; ++hf)
                        #pragma unroll
                        for (int mt = 0; mt < 2; ++mt)
                            mma_f16(acc[mt][nt2 * 2 + hf], af[mt],
                                    bfr[kh][nt2][hf*2], bfr[kh][nt2][hf*2+1]);
            }

            // store x_{t+1} into A[nxt] x-region
            if (t + 1 < T_LEN) {
                if (l == 0) {
                    #pragma unroll
                    for (int i = 0; i < 2; ++i) {
                        int gidx = tid + i * THREADS;
                        int n = gidx >> 3, k8 = (gidx & 7) * 8;
                        cvt8_store_f16(xv + i * 8, smem, SAn, swzoff(8, n, k8));
                    }
                } else {
                    #pragma unroll
                    for (int i = 0; i < 2; ++i) {
                        int gidx = tid + i * THREADS;
                        int n = gidx >> 3, k8 = (gidx & 7) * 8;
                        *(uint4*)(smem + SAn + swzoff(8, n, k8)) = xh[i];
                    }
                }
            }

            // epilogue: cell update; h -> GMEM + A[nxt] h-region
            #pragma unroll
            for (int mt = 0; mt < 2; ++mt)
                #pragma unroll
                for (int rh = 0; rh < 2; ++rh) {
                    int rowL = mrow0 + mt * 16 + gid + rh * 8;
                    float iv[4], fv[4], gv[4], ov[4];
                    #pragma unroll
                    for (int jo = 0; jo < 4; ++jo) {
                        iv[jo] = acc[mt][2*jo  ][rh*2 + 0];
                        fv[jo] = acc[mt][2*jo  ][rh*2 + 1];
                        gv[jo] = acc[mt][2*jo+1][rh*2 + 0];
                        ov[jo] = acc[mt][2*jo+1][rh*2 + 1];
                    }
                    // tanh(g) via f16x2 (output feeds fp16-bound h / bounded c term)
                    float2 tg01 = tanh2(gv[0], gv[1]);
                    float2 tg23 = tanh2(gv[2], gv[3]);
                    float tg[4] = {tg01.x, tg01.y, tg23.x, tg23.y};
                    float cc[4];
                    #pragma unroll
                    for (int jo = 0; jo < 4; ++jo) {
                        cc[jo] = siga(fv[jo]) * c_reg[mt][rh][jo]
                               + siga(iv[jo]) * tg[jo];
                        c_reg[mt][rh][jo] = cc[jo];
                    }
                    float2 tc01 = tanh2(cc[0], cc[1]);
                    float2 tc23 = tanh2(cc[2], cc[3]);
                    float tc[4] = {tc01.x, tc01.y, tc23.x, tc23.y};
                    float hv[4];
                    #pragma unroll
                    for (int jo = 0; jo < 4; ++jo)
                        hv[jo] = siga(ov[jo]) * tc[jo];

                    __half2 h0p = __floats2half2_rn(hv[0], hv[1]);
                    __half2 h1p = __floats2half2_rn(hv[2], hv[3]);
                    uint2 hp = make_uint2(*(uint32_t*)&h0p, *(uint32_t*)&h1p);
                    *(uint2*)(out_base + ((size_t)t * N_NODES + node0 + rowL) * H_DIM + jg) = hp;
                    *(uint2*)(smem + SAn + swzoff(8, rowL, 64 + jg)) = hp;
                }
            __syncthreads();   // all A[nxt] writes visible before next step's MMA
        }
        __threadfence();
        __syncthreads();
    }
}

// out[o][n][hd] = sum_c hs1[c][n][hd] * conv_w[o][c] + conv_b[o]
__global__ __launch_bounds__(256)
void conv_kernel(const float* __restrict__ conv_w,
                 const float* __restrict__ conv_b,
                 float* __restrict__ out)
{
    __shared__ float sw[T_LEN * N_HEADS * T_LEN];
    __shared__ float sb[T_LEN];
    for (int i = threadIdx.x; i < T_LEN * N_HEADS * T_LEN; i += 256)
        sw[i] = conv_w[i];
    if (threadIdx.x < T_LEN) sb[threadIdx.x] = conv_b[threadIdx.x];
    __syncthreads();

    const size_t stride = (size_t)N_NODES * H_DIM;
    size_t nh4 = ((size_t)blockIdx.x * 256 + threadIdx.x) * 4;

    float acc[T_LEN][4];
    #pragma unroll
    for (int o = 0; o < T_LEN; ++o) {
        float b = sb[o];
        acc[o][0] = b; acc[o][1] = b; acc[o][2] = b; acc[o][3] = b;
    }
    #pragma unroll 4
    for (int c = 0; c < N_HEADS * T_LEN; ++c) {
        uint2 raw = *(const uint2*)(g_hs1 + (size_t)c * stride + nh4);
        float2 f0 = __half22float2(*(__half2*)&raw.x);
        float2 f1 = __half22float2(*(__half2*)&raw.y);
        #pragma unroll
        for (int o = 0; o < T_LEN; ++o) {
            float w = sw[o * (N_HEADS * T_LEN) + c];
            acc[o][0] += f0.x * w; acc[o][1] += f0.y * w;
            acc[o][2] += f1.x * w; acc[o][3] += f1.y * w;
        }
    }
    #pragma unroll
    for (int o = 0; o < T_LEN; ++o)
        *(float4*)(out + (size_t)o * stride + nh4) =
            make_float4(acc[o][0], acc[o][1], acc[o][2], acc[o][3]);
}

extern "C" void kernel_launch(void* const* d_in, const int* in_sizes, int n_in,
                              void* d_out, int out_size)
{
    const float* x      = (const float*)d_in[0];
    const float* W_ih   = (const float*)d_in[1];
    const float* W_hh   = (const float*)d_in[2];
    const float* b_ih   = (const float*)d_in[3];
    const float* b_hh   = (const float*)d_in[4];
    const float* h0     = (const float*)d_in[5];
    const float* c0     = (const float*)d_in[6];
    const float* conv_w = (const float*)d_in[7];
    const float* conv_b = (const float*)d_in[8];
    float* out = (float*)d_out;

    cudaFuncSetAttribute(lstm_mma_kernel,
                         cudaFuncAttributeMaxDynamicSharedMemorySize, SMEM_TOTAL);

    dim3 grid(N_NODES / NB, N_HEADS);     // 256 x 8 = 2048 CTAs
    lstm_mma_kernel<<<grid, THREADS, SMEM_TOTAL>>>(x, W_ih, W_hh, b_ih, b_hh, h0, c0);

    conv_kernel<<<(N_NODES * H_DIM) / (4 * 256), 256>>>(conv_w, conv_b, out);
}